// round 6
// baseline (speedup 1.0000x reference)
#include <cuda_runtime.h>
#include <cuda_bf16.h>
#include <cstdint>

// Problem constants
#define BB   4
#define TT   2048
#define HH   16
#define SD   64
#define EE   1024
#define NROWS (BB*TT*HH)               // 131072 rows of 64
#define QK_SCALE 0.17677669529663687f  // 1 / 1024^0.25

// Scratch (device globals — no allocation allowed)
// q/k/v stored as split bf16 (hi + lo residual), layout [b,h,t,s]
__device__ __nv_bfloat16 g_qh[NROWS*SD], g_ql[NROWS*SD];
__device__ __nv_bfloat16 g_kh[NROWS*SD], g_kl[NROWS*SD];
__device__ __nv_bfloat16 g_vh[NROWS*SD], g_vl[NROWS*SD];
__device__ float g_ao[NROWS*SD];       // attention output fp32 [b,h,t,s]

// ---------------------------------------------------------------------------
// helpers
// ---------------------------------------------------------------------------
__device__ __forceinline__ uint32_t smem_u32(const void* p) {
    return (uint32_t)__cvta_generic_to_shared(p);
}
__device__ __forceinline__ void ldsm_x2(uint32_t& r0, uint32_t& r1, uint32_t a) {
    asm volatile("ldmatrix.sync.aligned.m8n8.x2.shared.b16 {%0,%1},[%2];"
                 : "=r"(r0), "=r"(r1) : "r"(a));
}
__device__ __forceinline__ void ldsm_x2_t(uint32_t& r0, uint32_t& r1, uint32_t a) {
    asm volatile("ldmatrix.sync.aligned.m8n8.x2.trans.shared.b16 {%0,%1},[%2];"
                 : "=r"(r0), "=r"(r1) : "r"(a));
}
__device__ __forceinline__ void ldsm_x4(uint32_t* r, uint32_t a) {
    asm volatile("ldmatrix.sync.aligned.m8n8.x4.shared.b16 {%0,%1,%2,%3},[%4];"
                 : "=r"(r[0]), "=r"(r[1]), "=r"(r[2]), "=r"(r[3]) : "r"(a));
}
// D += A * B (m16n8k16, bf16 in, f32 accum)
__device__ __forceinline__ void mma16816(float* d, const uint32_t* a,
                                         uint32_t b0, uint32_t b1) {
    asm volatile("mma.sync.aligned.m16n8k16.row.col.f32.bf16.bf16.f32 "
                 "{%0,%1,%2,%3},{%4,%5,%6,%7},{%8,%9},{%0,%1,%2,%3};"
                 : "+f"(d[0]), "+f"(d[1]), "+f"(d[2]), "+f"(d[3])
                 : "r"(a[0]), "r"(a[1]), "r"(a[2]), "r"(a[3]), "r"(b0), "r"(b1));
}
__device__ __forceinline__ uint32_t cvt2_bf16(float x, float y) {
    __nv_bfloat162 h = __floats2bfloat162_rn(x, y);
    return *reinterpret_cast<uint32_t*>(&h);
}
__device__ __forceinline__ uint32_t cvt2_bf16_lo(float x, float y, uint32_t hi) {
    __nv_bfloat162 h = *reinterpret_cast<__nv_bfloat162*>(&hi);
    return cvt2_bf16(x - __low2float(h), y - __high2float(h));
}

// ---------------------------------------------------------------------------
// Kernel 1: QKV projections (fp32 SIMT, already at FFMA roofline).
// x is [b,t,h,s] == flat [131072][64]. Outputs split-bf16 q/k/v in [b,h,t,s].
// ---------------------------------------------------------------------------
#define SWZ4(r, c4) (((r) << 4) + ((c4) ^ (((r) >> 2) & 15)))
#define DOT4(acc, A, W) \
    acc += (A).x * (W).x + (A).y * (W).y + (A).z * (W).z + (A).w * (W).w;

__global__ __launch_bounds__(256) void qkv_kernel(
    const float* __restrict__ x,
    const float* __restrict__ Wk,
    const float* __restrict__ Wq,
    const float* __restrict__ Wv)
{
    __shared__ float4 Xs[64 * 16];
    __shared__ float4 Ws[64 * 16];

    const int tid = threadIdx.x;
    const int ty = tid >> 4;
    const int tx = tid & 15;
    const int row0 = blockIdx.x * 64;

    const float4* xg = (const float4*)(x + (long)row0 * 64);
    #pragma unroll
    for (int i = 0; i < 4; i++) Xs[tid + 256 * i] = xg[tid + 256 * i];

    const float* Wlist[3] = {Wq, Wk, Wv};
    const float  scl [3]  = {QK_SCALE, QK_SCALE, 1.0f};
    __nv_bfloat16* outh[3] = {g_qh, g_kh, g_vh};
    __nv_bfloat16* outl[3] = {g_ql, g_kl, g_vl};

    for (int mm = 0; mm < 3; mm++) {
        __syncthreads();
        const float4* Wg = (const float4*)Wlist[mm];
        #pragma unroll
        for (int ii = 0; ii < 4; ii++) {
            int i = tid + 256 * ii;
            Ws[SWZ4(i >> 4, i & 15)] = Wg[i];
        }
        __syncthreads();

        float acc[4][4];
        #pragma unroll
        for (int i = 0; i < 4; i++)
            #pragma unroll
            for (int j = 0; j < 4; j++) acc[i][j] = 0.f;

        #pragma unroll 4
        for (int k4 = 0; k4 < 16; k4++) {
            float4 a[4], w[4];
            #pragma unroll
            for (int i = 0; i < 4; i++) a[i] = Xs[(ty * 4 + i) * 16 + k4];
            #pragma unroll
            for (int j = 0; j < 4; j++) w[j] = Ws[(tx * 4 + j) * 16 + (k4 ^ tx)];
            #pragma unroll
            for (int i = 0; i < 4; i++)
                #pragma unroll
                for (int j = 0; j < 4; j++)
                    DOT4(acc[i][j], a[i], w[j]);
        }

        const float s = scl[mm];
        __nv_bfloat16* oh = outh[mm];
        __nv_bfloat16* ol = outl[mm];
        #pragma unroll
        for (int i = 0; i < 4; i++) {
            int r = row0 + ty * 4 + i;            // (b,t,h) flattened
            int b = r >> 15;
            int t = (r >> 4) & 2047;
            int h = r & 15;
            long obase = (((long)(b * HH + h)) * TT + t) * SD + tx * 4;
            float y0 = acc[i][0] * s, y1 = acc[i][1] * s;
            float y2 = acc[i][2] * s, y3 = acc[i][3] * s;
            uint32_t h01 = cvt2_bf16(y0, y1), h23 = cvt2_bf16(y2, y3);
            uint32_t l01 = cvt2_bf16_lo(y0, y1, h01), l23 = cvt2_bf16_lo(y2, y3, h23);
            *(uint32_t*)&oh[obase]     = h01;
            *(uint32_t*)&oh[obase + 2] = h23;
            *(uint32_t*)&ol[obase]     = l01;
            *(uint32_t*)&ol[obase + 2] = l23;
        }
    }
}

// ---------------------------------------------------------------------------
// Kernel 2: flash attention on tensor cores (split-bf16 HMMA).
// grid=(T/64, B*H), block=128 (4 warps). Warp w owns q-rows w*16..+15, all 64 n.
// Q fragments persistent in registers. K/V tiles in smem (XOR-granule swizzle).
// P kept in registers (acc layout == A-fragment layout).
// ---------------------------------------------------------------------------
__global__ __launch_bounds__(128) void attn_kernel()
{
    __shared__ alignas(16) __nv_bfloat16 sKh[64*64], sKl[64*64];
    __shared__ alignas(16) __nv_bfloat16 sVh[64*64], sVl[64*64];

    const int tid  = threadIdx.x;
    const int lane = tid & 31;
    const int warp = tid >> 5;
    const int qt   = blockIdx.x;
    const int bh   = blockIdx.y;
    const long base = (long)bh * TT * SD;

    const int t4  = lane & 3;          // col pair within n8 / k16
    const int r16 = lane >> 2;         // row within 8-row group
    const int rl  = lane & 7;
    const int sub = (lane >> 3) & 1;

    // --- persistent Q fragments (hi + lo), 4 k-chunks ---
    uint32_t QAh[4][4], QAl[4][4];
    {
        const __nv_bfloat16* qh = g_qh + base;
        const __nv_bfloat16* ql = g_ql + base;
        const int r0 = qt * 64 + warp * 16 + r16;
        #pragma unroll
        for (int kc = 0; kc < 4; kc++) {
            int c0 = kc * 16 + 2 * t4;
            QAh[kc][0] = *(const uint32_t*)(qh + (long)r0      * 64 + c0);
            QAh[kc][1] = *(const uint32_t*)(qh + (long)(r0 + 8)* 64 + c0);
            QAh[kc][2] = *(const uint32_t*)(qh + (long)r0      * 64 + c0 + 8);
            QAh[kc][3] = *(const uint32_t*)(qh + (long)(r0 + 8)* 64 + c0 + 8);
            QAl[kc][0] = *(const uint32_t*)(ql + (long)r0      * 64 + c0);
            QAl[kc][1] = *(const uint32_t*)(ql + (long)(r0 + 8)* 64 + c0);
            QAl[kc][2] = *(const uint32_t*)(ql + (long)r0      * 64 + c0 + 8);
            QAl[kc][3] = *(const uint32_t*)(ql + (long)(r0 + 8)* 64 + c0 + 8);
        }
    }

    float O[8][4];
    #pragma unroll
    for (int j = 0; j < 8; j++)
        #pragma unroll
        for (int c = 0; c < 4; c++) O[j][c] = 0.f;
    float mrow[2] = {-1e30f, -1e30f};
    float lrow[2] = {0.f, 0.f};

    const uint32_t aKh = smem_u32(sKh), aKl = smem_u32(sKl);
    const uint32_t aVh = smem_u32(sVh), aVl = smem_u32(sVl);

    for (int kt = 0; kt < TT / 64; kt++) {
        __syncthreads();
        {   // load K/V tiles (bf16 hi/lo) with 16B-granule XOR swizzle
            const uint4* gkh = (const uint4*)(g_kh + base + kt * 4096);
            const uint4* gkl = (const uint4*)(g_kl + base + kt * 4096);
            const uint4* gvh = (const uint4*)(g_vh + base + kt * 4096);
            const uint4* gvl = (const uint4*)(g_vl + base + kt * 4096);
            #pragma unroll
            for (int it = 0; it < 4; it++) {
                int idx = it * 128 + tid;           // granule id 0..511
                int row = idx >> 3, g = idx & 7;
                int dst = row * 8 + (g ^ (row & 7));
                ((uint4*)sKh)[dst] = gkh[idx];
                ((uint4*)sKl)[dst] = gkl[idx];
                ((uint4*)sVh)[dst] = gvh[idx];
                ((uint4*)sVl)[dst] = gvl[idx];
            }
        }
        __syncthreads();

        // ---- S = Q K^T ----
        float S[8][4];
        #pragma unroll
        for (int j = 0; j < 8; j++)
            #pragma unroll
            for (int c = 0; c < 4; c++) S[j][c] = 0.f;

        #pragma unroll
        for (int kc = 0; kc < 4; kc++) {
            #pragma unroll
            for (int j = 0; j < 8; j++) {
                uint32_t off = (uint32_t)((8 * j + rl) * 128 +
                                          (((2 * kc + sub) ^ rl) * 16));
                uint32_t b0h, b1h, b0l, b1l;
                ldsm_x2(b0h, b1h, aKh + off);
                ldsm_x2(b0l, b1l, aKl + off);
                mma16816(S[j], QAh[kc], b0h, b1h);
                mma16816(S[j], QAh[kc], b0l, b1l);
                mma16816(S[j], QAl[kc], b0h, b1h);
            }
        }

        // ---- online softmax (warp-local) ----
        #pragma unroll
        for (int hh = 0; hh < 2; hh++) {
            float mx = -1e30f;
            #pragma unroll
            for (int j = 0; j < 8; j++)
                mx = fmaxf(mx, fmaxf(S[j][2*hh], S[j][2*hh+1]));
            mx = fmaxf(mx, __shfl_xor_sync(0xffffffffu, mx, 1));
            mx = fmaxf(mx, __shfl_xor_sync(0xffffffffu, mx, 2));
            float mn   = fmaxf(mrow[hh], mx);
            float corr = __expf(mrow[hh] - mn);
            float sum = 0.f;
            #pragma unroll
            for (int j = 0; j < 8; j++) {
                S[j][2*hh]   = __expf(S[j][2*hh]   - mn);
                S[j][2*hh+1] = __expf(S[j][2*hh+1] - mn);
                sum += S[j][2*hh] + S[j][2*hh+1];
            }
            sum += __shfl_xor_sync(0xffffffffu, sum, 1);
            sum += __shfl_xor_sync(0xffffffffu, sum, 2);
            lrow[hh] = lrow[hh] * corr + sum;
            mrow[hh] = mn;
            #pragma unroll
            for (int j = 0; j < 8; j++) {
                O[j][2*hh]   *= corr;
                O[j][2*hh+1] *= corr;
            }
        }

        // ---- P (registers): acc layout -> A-fragment layout ----
        uint32_t PAh[4][4], PAl[4][4];
        #pragma unroll
        for (int nc = 0; nc < 4; nc++) {
            const float* s0 = S[2*nc];
            const float* s1 = S[2*nc+1];
            PAh[nc][0] = cvt2_bf16(s0[0], s0[1]);
            PAh[nc][1] = cvt2_bf16(s0[2], s0[3]);
            PAh[nc][2] = cvt2_bf16(s1[0], s1[1]);
            PAh[nc][3] = cvt2_bf16(s1[2], s1[3]);
            PAl[nc][0] = cvt2_bf16_lo(s0[0], s0[1], PAh[nc][0]);
            PAl[nc][1] = cvt2_bf16_lo(s0[2], s0[3], PAh[nc][1]);
            PAl[nc][2] = cvt2_bf16_lo(s1[0], s1[1], PAh[nc][2]);
            PAl[nc][3] = cvt2_bf16_lo(s1[2], s1[3], PAh[nc][3]);
        }

        // ---- O += P V ----
        #pragma unroll
        for (int nc = 0; nc < 4; nc++) {
            #pragma unroll
            for (int j = 0; j < 8; j++) {
                uint32_t off = (uint32_t)((16 * nc + (lane & 15)) * 128 +
                                          ((j ^ rl) * 16));
                uint32_t v0h, v1h, v0l, v1l;
                ldsm_x2_t(v0h, v1h, aVh + off);
                ldsm_x2_t(v0l, v1l, aVl + off);
                mma16816(O[j], PAh[nc], v0h, v1h);
                mma16816(O[j], PAh[nc], v0l, v1l);
                mma16816(O[j], PAl[nc], v0h, v1h);
            }
        }
    }

    // ---- epilogue ----
    {
        float inv0 = 1.0f / lrow[0];
        float inv1 = 1.0f / lrow[1];
        float* ob = g_ao + base;
        const int r0 = qt * 64 + warp * 16 + r16;
        #pragma unroll
        for (int j = 0; j < 8; j++) {
            int c = 8 * j + 2 * t4;
            float2 v0 = make_float2(O[j][0] * inv0, O[j][1] * inv0);
            float2 v1 = make_float2(O[j][2] * inv1, O[j][3] * inv1);
            *(float2*)&ob[(long)r0      * 64 + c] = v0;
            *(float2*)&ob[(long)(r0 + 8)* 64 + c] = v1;
        }
    }
}

// ---------------------------------------------------------------------------
// Kernel 3: unify GEMM on tensor cores (split-bf16).
// out[row][n] = sum_k A[row][k] * Wu[n][k] + bu[n], A = g_ao permuted
// (k-tile 64 == one head -> contiguous 64x64 block). grid=(16,128), 4 warps.
// ---------------------------------------------------------------------------
__global__ __launch_bounds__(128) void unify_kernel(
    const float* __restrict__ Wu,
    const float* __restrict__ bu,
    float* __restrict__ out)
{
    __shared__ alignas(16) __nv_bfloat16 sAh[64*64], sAl[64*64];
    __shared__ alignas(16) __nv_bfloat16 sWh[64*64], sWl[64*64];

    const int tid  = threadIdx.x;
    const int lane = tid & 31;
    const int warp = tid >> 5;
    const int row0 = blockIdx.y * 64;
    const int col0 = blockIdx.x * 64;
    const int b    = row0 >> 11;       // tiles never straddle b
    const int t0   = row0 & 2047;

    const int t4  = lane & 3;
    const int r16 = lane >> 2;
    const int rl  = lane & 7;
    const int sub  = (lane >> 3) & 1;
    const int half = (lane >> 3) & 1;
    const int kh   = (lane >> 4) & 1;

    float acc[8][4];
    #pragma unroll
    for (int j = 0; j < 8; j++)
        #pragma unroll
        for (int c = 0; c < 4; c++) acc[j][c] = 0.f;

    const uint32_t aAh = smem_u32(sAh), aAl = smem_u32(sAl);
    const uint32_t aWh = smem_u32(sWh), aWl = smem_u32(sWl);

    for (int h = 0; h < HH; h++) {
        __syncthreads();
        {
            const float* ag = g_ao + ((long)(b * HH + h)) * TT * SD + (long)t0 * SD;
            const float* wg = Wu + (long)col0 * EE + h * 64;
            #pragma unroll
            for (int it = 0; it < 4; it++) {
                int idx = it * 128 + tid;       // granule id 0..511
                int row = idx >> 3, g = idx & 7;
                int dst = (row * 8 + (g ^ (row & 7))) * 8;  // element offset

                float4 a0 = *(const float4*)(ag + row * 64 + g * 8);
                float4 a1 = *(const float4*)(ag + row * 64 + g * 8 + 4);
                uint32_t h01 = cvt2_bf16(a0.x, a0.y), h23 = cvt2_bf16(a0.z, a0.w);
                uint32_t h45 = cvt2_bf16(a1.x, a1.y), h67 = cvt2_bf16(a1.z, a1.w);
                *(uint4*)&sAh[dst] = make_uint4(h01, h23, h45, h67);
                *(uint4*)&sAl[dst] = make_uint4(
                    cvt2_bf16_lo(a0.x, a0.y, h01), cvt2_bf16_lo(a0.z, a0.w, h23),
                    cvt2_bf16_lo(a1.x, a1.y, h45), cvt2_bf16_lo(a1.z, a1.w, h67));

                float4 w0 = *(const float4*)(wg + (long)row * EE + g * 8);
                float4 w1 = *(const float4*)(wg + (long)row * EE + g * 8 + 4);
                uint32_t wh01 = cvt2_bf16(w0.x, w0.y), wh23 = cvt2_bf16(w0.z, w0.w);
                uint32_t wh45 = cvt2_bf16(w1.x, w1.y), wh67 = cvt2_bf16(w1.z, w1.w);
                *(uint4*)&sWh[dst] = make_uint4(wh01, wh23, wh45, wh67);
                *(uint4*)&sWl[dst] = make_uint4(
                    cvt2_bf16_lo(w0.x, w0.y, wh01), cvt2_bf16_lo(w0.z, w0.w, wh23),
                    cvt2_bf16_lo(w1.x, w1.y, wh45), cvt2_bf16_lo(w1.z, w1.w, wh67));
            }
        }
        __syncthreads();

        #pragma unroll
        for (int kc = 0; kc < 4; kc++) {
            // A fragments (x4 ldmatrix)
            int arow = warp * 16 + rl + 8 * half;
            uint32_t offA = (uint32_t)(arow * 128 + (((2 * kc + kh) ^ rl) * 16));
            uint32_t Ah[4], Al[4];
            ldsm_x4(Ah, aAh + offA);
            ldsm_x4(Al, aAl + offA);
            #pragma unroll
            for (int j = 0; j < 8; j++) {
                uint32_t offW = (uint32_t)((8 * j + rl) * 128 +
                                           (((2 * kc + sub) ^ rl) * 16));
                uint32_t w0h, w1h, w0l, w1l;
                ldsm_x2(w0h, w1h, aWh + offW);
                ldsm_x2(w0l, w1l, aWl + offW);
                mma16816(acc[j], Ah, w0h, w1h);
                mma16816(acc[j], Ah, w0l, w1l);
                mma16816(acc[j], Al, w0h, w1h);
            }
        }
    }

    // store + bias
    {
        const int r0g = row0 + warp * 16 + r16;
        #pragma unroll
        for (int j = 0; j < 8; j++) {
            int c = col0 + 8 * j + 2 * t4;
            float2 bias = *(const float2*)&bu[c];
            float2 v0 = make_float2(acc[j][0] + bias.x, acc[j][1] + bias.y);
            float2 v1 = make_float2(acc[j][2] + bias.x, acc[j][3] + bias.y);
            *(float2*)&out[(long)r0g      * EE + c] = v0;
            *(float2*)&out[(long)(r0g + 8)* EE + c] = v1;
        }
    }
}

// ---------------------------------------------------------------------------
extern "C" void kernel_launch(void* const* d_in, const int* in_sizes, int n_in,
                              void* d_out, int out_size)
{
    const float* x  = (const float*)d_in[0];
    const float* Wk = (const float*)d_in[1];
    const float* Wq = (const float*)d_in[2];
    const float* Wv = (const float*)d_in[3];
    const float* Wu = (const float*)d_in[4];
    const float* bu = (const float*)d_in[5];
    float* out = (float*)d_out;

    qkv_kernel<<<NROWS / 64, 256>>>(x, Wk, Wq, Wv);
    attn_kernel<<<dim3(TT / 64, BB * HH), 128>>>();
    unify_kernel<<<dim3(EE / 64, (BB * TT) / 64), 128>>>(Wu, bu, out);
}

// round 7
// speedup vs baseline: 1.2466x; 1.2466x over previous
#include <cuda_runtime.h>
#include <cuda_bf16.h>
#include <cstdint>

// Problem constants
#define BB   4
#define TT   2048
#define HH   16
#define SD   64
#define EE   1024
#define NROWS (BB*TT*HH)               // 131072 rows of 64
#define QK_SCALE 0.17677669529663687f  // 1 / 1024^0.25

// Scratch (device globals — no allocation allowed), all split bf16 (hi + lo)
__device__ __align__(16) __nv_bfloat16 g_qh[NROWS*SD], g_ql[NROWS*SD];
__device__ __align__(16) __nv_bfloat16 g_kh[NROWS*SD], g_kl[NROWS*SD];
__device__ __align__(16) __nv_bfloat16 g_vh[NROWS*SD], g_vl[NROWS*SD];
__device__ __align__(16) __nv_bfloat16 g_aoh[NROWS*SD], g_aol[NROWS*SD];
__device__ __align__(16) __nv_bfloat16 g_wh[EE*EE], g_wl[EE*EE];

// ---------------------------------------------------------------------------
// helpers
// ---------------------------------------------------------------------------
__device__ __forceinline__ uint32_t smem_u32(const void* p) {
    return (uint32_t)__cvta_generic_to_shared(p);
}
__device__ __forceinline__ void ldsm_x2(uint32_t& r0, uint32_t& r1, uint32_t a) {
    asm volatile("ldmatrix.sync.aligned.m8n8.x2.shared.b16 {%0,%1},[%2];"
                 : "=r"(r0), "=r"(r1) : "r"(a));
}
__device__ __forceinline__ void ldsm_x2_t(uint32_t& r0, uint32_t& r1, uint32_t a) {
    asm volatile("ldmatrix.sync.aligned.m8n8.x2.trans.shared.b16 {%0,%1},[%2];"
                 : "=r"(r0), "=r"(r1) : "r"(a));
}
__device__ __forceinline__ void ldsm_x4(uint32_t* r, uint32_t a) {
    asm volatile("ldmatrix.sync.aligned.m8n8.x4.shared.b16 {%0,%1,%2,%3},[%4];"
                 : "=r"(r[0]), "=r"(r[1]), "=r"(r[2]), "=r"(r[3]) : "r"(a));
}
__device__ __forceinline__ void mma16816(float* d, const uint32_t* a,
                                         uint32_t b0, uint32_t b1) {
    asm volatile("mma.sync.aligned.m16n8k16.row.col.f32.bf16.bf16.f32 "
                 "{%0,%1,%2,%3},{%4,%5,%6,%7},{%8,%9},{%0,%1,%2,%3};"
                 : "+f"(d[0]), "+f"(d[1]), "+f"(d[2]), "+f"(d[3])
                 : "r"(a[0]), "r"(a[1]), "r"(a[2]), "r"(a[3]), "r"(b0), "r"(b1));
}
__device__ __forceinline__ uint32_t cvt2_bf16(float x, float y) {
    __nv_bfloat162 h = __floats2bfloat162_rn(x, y);
    return *reinterpret_cast<uint32_t*>(&h);
}
__device__ __forceinline__ uint32_t cvt2_bf16_lo(float x, float y, uint32_t hi) {
    __nv_bfloat162 h = *reinterpret_cast<__nv_bfloat162*>(&hi);
    return cvt2_bf16(x - __low2float(h), y - __high2float(h));
}
__device__ __forceinline__ void cp16(uint32_t dst, const void* src) {
    asm volatile("cp.async.cg.shared.global [%0], [%1], 16;"
                 :: "r"(dst), "l"(src));
}
__device__ __forceinline__ void cp_commit() {
    asm volatile("cp.async.commit_group;");
}
template <int N> __device__ __forceinline__ void cp_wait() {
    asm volatile("cp.async.wait_group %0;" :: "n"(N));
}

// ---------------------------------------------------------------------------
// Kernel 0: convert Wu -> split bf16 (once; removes per-block redundant cvt)
// ---------------------------------------------------------------------------
__global__ __launch_bounds__(256) void wprep_kernel(const float* __restrict__ Wu)
{
    int i = blockIdx.x * 256 + threadIdx.x;     // one float4 each
    float4 v = ((const float4*)Wu)[i];
    uint32_t h01 = cvt2_bf16(v.x, v.y), h23 = cvt2_bf16(v.z, v.w);
    ((uint2*)g_wh)[i] = make_uint2(h01, h23);
    ((uint2*)g_wl)[i] = make_uint2(cvt2_bf16_lo(v.x, v.y, h01),
                                   cvt2_bf16_lo(v.z, v.w, h23));
}

// ---------------------------------------------------------------------------
// Kernel 1: QKV projections (fp32 SIMT, at FFMA roofline).
// x is [b,t,h,s] flat [131072][64]. Emits split-bf16 q/k/v in [b,h,t,s].
// ---------------------------------------------------------------------------
#define SWZ4(r, c4) (((r) << 4) + ((c4) ^ (((r) >> 2) & 15)))
#define DOT4(acc, A, W) \
    acc += (A).x * (W).x + (A).y * (W).y + (A).z * (W).z + (A).w * (W).w;

__global__ __launch_bounds__(256) void qkv_kernel(
    const float* __restrict__ x,
    const float* __restrict__ Wk,
    const float* __restrict__ Wq,
    const float* __restrict__ Wv)
{
    __shared__ float4 Xs[64 * 16];
    __shared__ float4 Ws[64 * 16];

    const int tid = threadIdx.x;
    const int ty = tid >> 4;
    const int tx = tid & 15;
    const int row0 = blockIdx.x * 64;

    const float4* xg = (const float4*)(x + (long)row0 * 64);
    #pragma unroll
    for (int i = 0; i < 4; i++) Xs[tid + 256 * i] = xg[tid + 256 * i];

    const float* Wlist[3] = {Wq, Wk, Wv};
    const float  scl [3]  = {QK_SCALE, QK_SCALE, 1.0f};
    __nv_bfloat16* outh[3] = {g_qh, g_kh, g_vh};
    __nv_bfloat16* outl[3] = {g_ql, g_kl, g_vl};

    for (int mm = 0; mm < 3; mm++) {
        __syncthreads();
        const float4* Wg = (const float4*)Wlist[mm];
        #pragma unroll
        for (int ii = 0; ii < 4; ii++) {
            int i = tid + 256 * ii;
            Ws[SWZ4(i >> 4, i & 15)] = Wg[i];
        }
        __syncthreads();

        float acc[4][4];
        #pragma unroll
        for (int i = 0; i < 4; i++)
            #pragma unroll
            for (int j = 0; j < 4; j++) acc[i][j] = 0.f;

        #pragma unroll 4
        for (int k4 = 0; k4 < 16; k4++) {
            float4 a[4], w[4];
            #pragma unroll
            for (int i = 0; i < 4; i++) a[i] = Xs[(ty * 4 + i) * 16 + k4];
            #pragma unroll
            for (int j = 0; j < 4; j++) w[j] = Ws[(tx * 4 + j) * 16 + (k4 ^ tx)];
            #pragma unroll
            for (int i = 0; i < 4; i++)
                #pragma unroll
                for (int j = 0; j < 4; j++)
                    DOT4(acc[i][j], a[i], w[j]);
        }

        const float s = scl[mm];
        __nv_bfloat16* oh = outh[mm];
        __nv_bfloat16* ol = outl[mm];
        #pragma unroll
        for (int i = 0; i < 4; i++) {
            int r = row0 + ty * 4 + i;            // (b,t,h) flattened
            int b = r >> 15;
            int t = (r >> 4) & 2047;
            int h = r & 15;
            long obase = (((long)(b * HH + h)) * TT + t) * SD + tx * 4;
            float y0 = acc[i][0] * s, y1 = acc[i][1] * s;
            float y2 = acc[i][2] * s, y3 = acc[i][3] * s;
            uint32_t h01 = cvt2_bf16(y0, y1), h23 = cvt2_bf16(y2, y3);
            *(uint32_t*)&oh[obase]     = h01;
            *(uint32_t*)&oh[obase + 2] = h23;
            *(uint32_t*)&ol[obase]     = cvt2_bf16_lo(y0, y1, h01);
            *(uint32_t*)&ol[obase + 2] = cvt2_bf16_lo(y2, y3, h23);
        }
    }
}

// ---------------------------------------------------------------------------
// Kernel 2: flash attention, split-bf16 HMMA, cp.async double-buffered K/V.
// grid=(T/64, B*H), block=128. Dynamic smem 64KB:
//   [Kh s0|Kh s1|Kl s0|Kl s1|Vh s0|Vh s1|Vl s0|Vl s1], 8KB each tile stage.
// ---------------------------------------------------------------------------
#define NT (TT / 64)

__global__ __launch_bounds__(128) void attn_kernel()
{
    extern __shared__ __align__(16) char smem[];
    const uint32_t aS  = smem_u32(smem);
    const uint32_t aKh = aS, aKl = aS + 16384;
    const uint32_t aVh = aS + 32768, aVl = aS + 49152;

    const int tid  = threadIdx.x;
    const int lane = tid & 31;
    const int warp = tid >> 5;
    const int qt   = blockIdx.x;
    const int bh   = blockIdx.y;
    const long base = (long)bh * TT * SD;

    const int t4  = lane & 3;
    const int r16 = lane >> 2;
    const int rl  = lane & 7;
    const int sub = (lane >> 3) & 1;

    // tile prefetch (16B granules with XOR swizzle)
    auto load_tile = [&](int kt, int st) {
        const char* gkh = (const char*)(g_kh + base + kt * 4096);
        const char* gkl = (const char*)(g_kl + base + kt * 4096);
        const char* gvh = (const char*)(g_vh + base + kt * 4096);
        const char* gvl = (const char*)(g_vl + base + kt * 4096);
        const uint32_t so = (uint32_t)st * 8192;
        #pragma unroll
        for (int it = 0; it < 4; it++) {
            int idx = it * 128 + tid;
            int row = idx >> 3, g = idx & 7;
            uint32_t d = (uint32_t)((row * 8 + (g ^ (row & 7))) * 16) + so;
            cp16(aKh + d, gkh + idx * 16);
            cp16(aKl + d, gkl + idx * 16);
            cp16(aVh + d, gvh + idx * 16);
            cp16(aVl + d, gvl + idx * 16);
        }
    };

    // persistent Q fragments
    uint32_t QAh[4][4], QAl[4][4];
    {
        const __nv_bfloat16* qh = g_qh + base;
        const __nv_bfloat16* ql = g_ql + base;
        const int r0 = qt * 64 + warp * 16 + r16;
        #pragma unroll
        for (int kc = 0; kc < 4; kc++) {
            int c0 = kc * 16 + 2 * t4;
            QAh[kc][0] = *(const uint32_t*)(qh + (long)r0      * 64 + c0);
            QAh[kc][1] = *(const uint32_t*)(qh + (long)(r0 + 8)* 64 + c0);
            QAh[kc][2] = *(const uint32_t*)(qh + (long)r0      * 64 + c0 + 8);
            QAh[kc][3] = *(const uint32_t*)(qh + (long)(r0 + 8)* 64 + c0 + 8);
            QAl[kc][0] = *(const uint32_t*)(ql + (long)r0      * 64 + c0);
            QAl[kc][1] = *(const uint32_t*)(ql + (long)(r0 + 8)* 64 + c0);
            QAl[kc][2] = *(const uint32_t*)(ql + (long)r0      * 64 + c0 + 8);
            QAl[kc][3] = *(const uint32_t*)(ql + (long)(r0 + 8)* 64 + c0 + 8);
        }
    }

    float O[8][4];
    #pragma unroll
    for (int j = 0; j < 8; j++)
        #pragma unroll
        for (int c = 0; c < 4; c++) O[j][c] = 0.f;
    float mrow[2] = {-1e30f, -1e30f};
    float lrow[2] = {0.f, 0.f};

    load_tile(0, 0);
    cp_commit();

    for (int kt = 0; kt < NT; kt++) {
        const int st = kt & 1;
        const uint32_t so = (uint32_t)st * 8192;
        if (kt + 1 < NT) {
            load_tile(kt + 1, st ^ 1);
            cp_commit();
            cp_wait<1>();
        } else {
            cp_wait<0>();
        }
        __syncthreads();

        // ---- S = Q K^T ----
        float S[8][4];
        #pragma unroll
        for (int j = 0; j < 8; j++)
            #pragma unroll
            for (int c = 0; c < 4; c++) S[j][c] = 0.f;

        #pragma unroll
        for (int kc = 0; kc < 4; kc++) {
            #pragma unroll
            for (int j = 0; j < 8; j++) {
                uint32_t off = (uint32_t)((8 * j + rl) * 128 +
                                          (((2 * kc + sub) ^ rl) * 16)) + so;
                uint32_t b0h, b1h, b0l, b1l;
                ldsm_x2(b0h, b1h, aKh + off);
                ldsm_x2(b0l, b1l, aKl + off);
                mma16816(S[j], QAh[kc], b0h, b1h);
                mma16816(S[j], QAh[kc], b0l, b1l);
                mma16816(S[j], QAl[kc], b0h, b1h);
            }
        }

        // ---- online softmax (warp-local) ----
        #pragma unroll
        for (int hh = 0; hh < 2; hh++) {
            float mx = -1e30f;
            #pragma unroll
            for (int j = 0; j < 8; j++)
                mx = fmaxf(mx, fmaxf(S[j][2*hh], S[j][2*hh+1]));
            mx = fmaxf(mx, __shfl_xor_sync(0xffffffffu, mx, 1));
            mx = fmaxf(mx, __shfl_xor_sync(0xffffffffu, mx, 2));
            float mn   = fmaxf(mrow[hh], mx);
            float corr = __expf(mrow[hh] - mn);
            float sum = 0.f;
            #pragma unroll
            for (int j = 0; j < 8; j++) {
                S[j][2*hh]   = __expf(S[j][2*hh]   - mn);
                S[j][2*hh+1] = __expf(S[j][2*hh+1] - mn);
                sum += S[j][2*hh] + S[j][2*hh+1];
            }
            sum += __shfl_xor_sync(0xffffffffu, sum, 1);
            sum += __shfl_xor_sync(0xffffffffu, sum, 2);
            lrow[hh] = lrow[hh] * corr + sum;
            mrow[hh] = mn;
            #pragma unroll
            for (int j = 0; j < 8; j++) {
                O[j][2*hh]   *= corr;
                O[j][2*hh+1] *= corr;
            }
        }

        // ---- P: acc layout -> A-fragment layout ----
        uint32_t PAh[4][4], PAl[4][4];
        #pragma unroll
        for (int nc = 0; nc < 4; nc++) {
            const float* s0 = S[2*nc];
            const float* s1 = S[2*nc+1];
            PAh[nc][0] = cvt2_bf16(s0[0], s0[1]);
            PAh[nc][1] = cvt2_bf16(s0[2], s0[3]);
            PAh[nc][2] = cvt2_bf16(s1[0], s1[1]);
            PAh[nc][3] = cvt2_bf16(s1[2], s1[3]);
            PAl[nc][0] = cvt2_bf16_lo(s0[0], s0[1], PAh[nc][0]);
            PAl[nc][1] = cvt2_bf16_lo(s0[2], s0[3], PAh[nc][1]);
            PAl[nc][2] = cvt2_bf16_lo(s1[0], s1[1], PAh[nc][2]);
            PAl[nc][3] = cvt2_bf16_lo(s1[2], s1[3], PAh[nc][3]);
        }

        // ---- O += P V ----
        #pragma unroll
        for (int nc = 0; nc < 4; nc++) {
            #pragma unroll
            for (int j = 0; j < 8; j++) {
                uint32_t off = (uint32_t)((16 * nc + (lane & 15)) * 128 +
                                          ((j ^ rl) * 16)) + so;
                uint32_t v0h, v1h, v0l, v1l;
                ldsm_x2_t(v0h, v1h, aVh + off);
                ldsm_x2_t(v0l, v1l, aVl + off);
                mma16816(O[j], PAh[nc], v0h, v1h);
                mma16816(O[j], PAh[nc], v0l, v1l);
                mma16816(O[j], PAl[nc], v0h, v1h);
            }
        }
        __syncthreads();   // stage reuse safety for next prefetch
    }

    // ---- epilogue: write split-bf16 attention output ----
    {
        float inv0 = 1.0f / lrow[0];
        float inv1 = 1.0f / lrow[1];
        __nv_bfloat16* obh = g_aoh + base;
        __nv_bfloat16* obl = g_aol + base;
        const int r0 = qt * 64 + warp * 16 + r16;
        #pragma unroll
        for (int j = 0; j < 8; j++) {
            int c = 8 * j + 2 * t4;
            float y0 = O[j][0] * inv0, y1 = O[j][1] * inv0;
            float y2 = O[j][2] * inv1, y3 = O[j][3] * inv1;
            uint32_t h0 = cvt2_bf16(y0, y1), h1 = cvt2_bf16(y2, y3);
            *(uint32_t*)&obh[(long)r0      * 64 + c] = h0;
            *(uint32_t*)&obh[(long)(r0 + 8)* 64 + c] = h1;
            *(uint32_t*)&obl[(long)r0      * 64 + c] = cvt2_bf16_lo(y0, y1, h0);
            *(uint32_t*)&obl[(long)(r0 + 8)* 64 + c] = cvt2_bf16_lo(y2, y3, h1);
        }
    }
}

// ---------------------------------------------------------------------------
// Kernel 3: unify GEMM, split-bf16 HMMA, cp.async double-buffered, no cvt.
// Dynamic smem 64KB: [Ah s0|s1 | Al | Wh | Wl]. grid=(16,128), block=128.
// ---------------------------------------------------------------------------
__global__ __launch_bounds__(128) void unify_kernel(
    const float* __restrict__ bu,
    float* __restrict__ out)
{
    extern __shared__ __align__(16) char smem[];
    const uint32_t aS  = smem_u32(smem);
    const uint32_t aAh = aS, aAl = aS + 16384;
    const uint32_t aWh = aS + 32768, aWl = aS + 49152;

    const int tid  = threadIdx.x;
    const int lane = tid & 31;
    const int warp = tid >> 5;
    const int row0 = blockIdx.y * 64;
    const int col0 = blockIdx.x * 64;
    const int b    = row0 >> 11;       // tiles never straddle b
    const int t0   = row0 & 2047;

    const int t4   = lane & 3;
    const int r16  = lane >> 2;
    const int rl   = lane & 7;
    const int sub  = (lane >> 3) & 1;
    const int half = (lane >> 3) & 1;
    const int kh   = (lane >> 4) & 1;

    auto load_tile = [&](int h, int st) {
        const char* gah = (const char*)(g_aoh + ((long)(b * HH + h)) * TT * SD
                                              + (long)t0 * SD);
        const char* gal = (const char*)(g_aol + ((long)(b * HH + h)) * TT * SD
                                              + (long)t0 * SD);
        const char* gwh = (const char*)(g_wh + (long)col0 * EE + h * 64);
        const char* gwl = (const char*)(g_wl + (long)col0 * EE + h * 64);
        const uint32_t so = (uint32_t)st * 8192;
        #pragma unroll
        for (int it = 0; it < 4; it++) {
            int idx = it * 128 + tid;
            int row = idx >> 3, g = idx & 7;
            uint32_t d = (uint32_t)((row * 8 + (g ^ (row & 7))) * 16) + so;
            cp16(aAh + d, gah + (row * 64 + g * 8) * 2);
            cp16(aAl + d, gal + (row * 64 + g * 8) * 2);
            cp16(aWh + d, gwh + (row * EE + g * 8) * 2);
            cp16(aWl + d, gwl + (row * EE + g * 8) * 2);
        }
    };

    float acc[8][4];
    #pragma unroll
    for (int j = 0; j < 8; j++)
        #pragma unroll
        for (int c = 0; c < 4; c++) acc[j][c] = 0.f;

    load_tile(0, 0);
    cp_commit();

    for (int h = 0; h < HH; h++) {
        const int st = h & 1;
        const uint32_t so = (uint32_t)st * 8192;
        if (h + 1 < HH) {
            load_tile(h + 1, st ^ 1);
            cp_commit();
            cp_wait<1>();
        } else {
            cp_wait<0>();
        }
        __syncthreads();

        #pragma unroll
        for (int kc = 0; kc < 4; kc++) {
            int arow = warp * 16 + rl + 8 * half;
            uint32_t offA = (uint32_t)(arow * 128 + (((2 * kc + kh) ^ rl) * 16)) + so;
            uint32_t Ah[4], Al[4];
            ldsm_x4(Ah, aAh + offA);
            ldsm_x4(Al, aAl + offA);
            #pragma unroll
            for (int j = 0; j < 8; j++) {
                uint32_t offW = (uint32_t)((8 * j + rl) * 128 +
                                           (((2 * kc + sub) ^ rl) * 16)) + so;
                uint32_t w0h, w1h, w0l, w1l;
                ldsm_x2(w0h, w1h, aWh + offW);
                ldsm_x2(w0l, w1l, aWl + offW);
                mma16816(acc[j], Ah, w0h, w1h);
                mma16816(acc[j], Ah, w0l, w1l);
                mma16816(acc[j], Al, w0h, w1h);
            }
        }
        __syncthreads();
    }

    // store + bias
    {
        const int r0g = row0 + warp * 16 + r16;
        #pragma unroll
        for (int j = 0; j < 8; j++) {
            int c = col0 + 8 * j + 2 * t4;
            float2 bias = *(const float2*)&bu[c];
            float2 v0 = make_float2(acc[j][0] + bias.x, acc[j][1] + bias.y);
            float2 v1 = make_float2(acc[j][2] + bias.x, acc[j][3] + bias.y);
            *(float2*)&out[(long)r0g      * EE + c] = v0;
            *(float2*)&out[(long)(r0g + 8)* EE + c] = v1;
        }
    }
}

// ---------------------------------------------------------------------------
extern "C" void kernel_launch(void* const* d_in, const int* in_sizes, int n_in,
                              void* d_out, int out_size)
{
    const float* x  = (const float*)d_in[0];
    const float* Wk = (const float*)d_in[1];
    const float* Wq = (const float*)d_in[2];
    const float* Wv = (const float*)d_in[3];
    const float* Wu = (const float*)d_in[4];
    const float* bu = (const float*)d_in[5];
    float* out = (float*)d_out;

    cudaFuncSetAttribute(attn_kernel,
                         cudaFuncAttributeMaxDynamicSharedMemorySize, 65536);
    cudaFuncSetAttribute(unify_kernel,
                         cudaFuncAttributeMaxDynamicSharedMemorySize, 65536);

    wprep_kernel<<<(EE * EE / 4) / 256, 256>>>(Wu);
    qkv_kernel<<<NROWS / 64, 256>>>(x, Wk, Wq, Wv);
    attn_kernel<<<dim3(TT / 64, BB * HH), 128, 65536>>>();
    unify_kernel<<<dim3(EE / 64, (BB * TT) / 64), 128, 65536>>>(bu, out);
}

// round 9
// speedup vs baseline: 1.5529x; 1.2457x over previous
#include <cuda_runtime.h>
#include <cuda_fp16.h>
#include <cstdint>

// Problem constants
#define BB   4
#define TT   2048
#define HH   16
#define SD   64
#define EE   1024
#define NROWS (BB*TT*HH)               // 131072 rows of 64
#define QK_SCALE 0.17677669529663687f  // 1 / 1024^0.25

// Scratch (device globals — no allocation allowed), fp16 formats:
//   q: hi + lo residual (2-term, exact to 2^-22)
//   k: single fp16
//   v: hi + lo residual
//   ao (attention out): single fp16
//   Wu: hi + lo residual
__device__ __align__(16) __half g_qh[NROWS*SD], g_ql[NROWS*SD];
__device__ __align__(16) __half g_kh[NROWS*SD];
__device__ __align__(16) __half g_vh[NROWS*SD], g_vl[NROWS*SD];
__device__ __align__(16) __half g_aoh[NROWS*SD];
__device__ __align__(16) __half g_wh[EE*EE], g_wl[EE*EE];

// ---------------------------------------------------------------------------
// helpers
// ---------------------------------------------------------------------------
__device__ __forceinline__ uint32_t smem_u32(const void* p) {
    return (uint32_t)__cvta_generic_to_shared(p);
}
__device__ __forceinline__ void ldsm_x2(uint32_t& r0, uint32_t& r1, uint32_t a) {
    asm volatile("ldmatrix.sync.aligned.m8n8.x2.shared.b16 {%0,%1},[%2];"
                 : "=r"(r0), "=r"(r1) : "r"(a));
}
__device__ __forceinline__ void ldsm_x2_t(uint32_t& r0, uint32_t& r1, uint32_t a) {
    asm volatile("ldmatrix.sync.aligned.m8n8.x2.trans.shared.b16 {%0,%1},[%2];"
                 : "=r"(r0), "=r"(r1) : "r"(a));
}
__device__ __forceinline__ void ldsm_x4(uint32_t* r, uint32_t a) {
    asm volatile("ldmatrix.sync.aligned.m8n8.x4.shared.b16 {%0,%1,%2,%3},[%4];"
                 : "=r"(r[0]), "=r"(r[1]), "=r"(r[2]), "=r"(r[3]) : "r"(a));
}
// D += A * B (m16n8k16, fp16 in, f32 accum)
__device__ __forceinline__ void mma16816(float* d, const uint32_t* a,
                                         uint32_t b0, uint32_t b1) {
    asm volatile("mma.sync.aligned.m16n8k16.row.col.f32.f16.f16.f32 "
                 "{%0,%1,%2,%3},{%4,%5,%6,%7},{%8,%9},{%0,%1,%2,%3};"
                 : "+f"(d[0]), "+f"(d[1]), "+f"(d[2]), "+f"(d[3])
                 : "r"(a[0]), "r"(a[1]), "r"(a[2]), "r"(a[3]), "r"(b0), "r"(b1));
}
__device__ __forceinline__ uint32_t cvt2_f16(float x, float y) {
    __half2 h = __floats2half2_rn(x, y);
    return *reinterpret_cast<uint32_t*>(&h);
}
__device__ __forceinline__ uint32_t cvt2_f16_lo(float x, float y, uint32_t hi) {
    __half2 h = *reinterpret_cast<__half2*>(&hi);
    return cvt2_f16(x - __low2float(h), y - __high2float(h));
}
__device__ __forceinline__ void cp16(uint32_t dst, const void* src) {
    asm volatile("cp.async.cg.shared.global [%0], [%1], 16;"
                 :: "r"(dst), "l"(src));
}
__device__ __forceinline__ void cp_commit() {
    asm volatile("cp.async.commit_group;");
}
template <int N> __device__ __forceinline__ void cp_wait() {
    asm volatile("cp.async.wait_group %0;" :: "n"(N));
}

// ---------------------------------------------------------------------------
// Kernel 0: convert Wu -> split fp16 (once)
// ---------------------------------------------------------------------------
__global__ __launch_bounds__(256) void wprep_kernel(const float* __restrict__ Wu)
{
    int i = blockIdx.x * 256 + threadIdx.x;     // one float4 each
    float4 v = ((const float4*)Wu)[i];
    uint32_t h01 = cvt2_f16(v.x, v.y), h23 = cvt2_f16(v.z, v.w);
    ((uint2*)g_wh)[i] = make_uint2(h01, h23);
    ((uint2*)g_wl)[i] = make_uint2(cvt2_f16_lo(v.x, v.y, h01),
                                   cvt2_f16_lo(v.z, v.w, h23));
}

// ---------------------------------------------------------------------------
// Kernel 1: QKV projections (fp32 SIMT, at FFMA roofline).
// x is [b,t,h,s] flat [131072][64]. Emits fp16 q(hi,lo), k(hi), v(hi,lo)
// in [b,h,t,s]. QK_SCALE folded into q and k.
// ---------------------------------------------------------------------------
#define SWZ4(r, c4) (((r) << 4) + ((c4) ^ (((r) >> 2) & 15)))
#define DOT4(acc, A, W) \
    acc += (A).x * (W).x + (A).y * (W).y + (A).z * (W).z + (A).w * (W).w;

__global__ __launch_bounds__(256) void qkv_kernel(
    const float* __restrict__ x,
    const float* __restrict__ Wk,
    const float* __restrict__ Wq,
    const float* __restrict__ Wv)
{
    __shared__ float4 Xs[64 * 16];
    __shared__ float4 Ws[64 * 16];

    const int tid = threadIdx.x;
    const int ty = tid >> 4;
    const int tx = tid & 15;
    const int row0 = blockIdx.x * 64;

    const float4* xg = (const float4*)(x + (long)row0 * 64);
    #pragma unroll
    for (int i = 0; i < 4; i++) Xs[tid + 256 * i] = xg[tid + 256 * i];

    const float* Wlist[3] = {Wq, Wk, Wv};
    const float  scl [3]  = {QK_SCALE, QK_SCALE, 1.0f};
    __half* outh[3] = {g_qh, g_kh, g_vh};
    __half* outl[3] = {g_ql, (__half*)0, g_vl};   // k has no lo plane

    for (int mm = 0; mm < 3; mm++) {
        __syncthreads();
        const float4* Wg = (const float4*)Wlist[mm];
        #pragma unroll
        for (int ii = 0; ii < 4; ii++) {
            int i = tid + 256 * ii;
            Ws[SWZ4(i >> 4, i & 15)] = Wg[i];
        }
        __syncthreads();

        float acc[4][4];
        #pragma unroll
        for (int i = 0; i < 4; i++)
            #pragma unroll
            for (int j = 0; j < 4; j++) acc[i][j] = 0.f;

        #pragma unroll 4
        for (int k4 = 0; k4 < 16; k4++) {
            float4 a[4], w[4];
            #pragma unroll
            for (int i = 0; i < 4; i++) a[i] = Xs[(ty * 4 + i) * 16 + k4];
            #pragma unroll
            for (int j = 0; j < 4; j++) w[j] = Ws[(tx * 4 + j) * 16 + (k4 ^ tx)];
            #pragma unroll
            for (int i = 0; i < 4; i++)
                #pragma unroll
                for (int j = 0; j < 4; j++)
                    DOT4(acc[i][j], a[i], w[j]);
        }

        const float s = scl[mm];
        __half* oh = outh[mm];
        __half* ol = outl[mm];
        #pragma unroll
        for (int i = 0; i < 4; i++) {
            int r = row0 + ty * 4 + i;            // (b,t,h) flattened
            int b = r >> 15;
            int t = (r >> 4) & 2047;
            int h = r & 15;
            long obase = (((long)(b * HH + h)) * TT + t) * SD + tx * 4;
            float y0 = acc[i][0] * s, y1 = acc[i][1] * s;
            float y2 = acc[i][2] * s, y3 = acc[i][3] * s;
            uint32_t h01 = cvt2_f16(y0, y1), h23 = cvt2_f16(y2, y3);
            *(uint32_t*)&oh[obase]     = h01;
            *(uint32_t*)&oh[obase + 2] = h23;
            if (ol) {
                *(uint32_t*)&ol[obase]     = cvt2_f16_lo(y0, y1, h01);
                *(uint32_t*)&ol[obase + 2] = cvt2_f16_lo(y2, y3, h23);
            }
        }
    }
}

// ---------------------------------------------------------------------------
// Kernel 2: flash attention, fp16 HMMA, 2 MMA terms per GEMM.
//   S = (qh + ql) * kh      (k single fp16)
//   O += Ph * (vh + vl)     (P single fp16)
// grid=(T/64, B*H), block=128. Dynamic smem 48KB:
// stage st at st*24576: [Kh 8KB | Vh 8KB | Vl 8KB]. cp.async double-buffered.
// ---------------------------------------------------------------------------
#define NT (TT / 64)
#define ASTG 24576

__global__ __launch_bounds__(128) void attn_kernel()
{
    extern __shared__ __align__(16) char smem[];
    const uint32_t aS = smem_u32(smem);

    const int tid  = threadIdx.x;
    const int lane = tid & 31;
    const int warp = tid >> 5;
    const int qt   = blockIdx.x;
    const int bh   = blockIdx.y;
    const long base = (long)bh * TT * SD;

    const int t4  = lane & 3;
    const int r16 = lane >> 2;
    const int rl  = lane & 7;
    const int sub = (lane >> 3) & 1;

    auto load_kv = [&](int kt, int st) {
        const __half* kh = g_kh + base + kt * 4096;
        const __half* vh = g_vh + base + kt * 4096;
        const __half* vl = g_vl + base + kt * 4096;
        const uint32_t so = aS + (uint32_t)st * ASTG;
        #pragma unroll
        for (int it = 0; it < 4; it++) {
            int idx = it * 128 + tid;
            int row = idx >> 3, g = idx & 7;
            uint32_t d = (uint32_t)(row * 128 + ((g ^ (row & 7)) * 16));
            cp16(so + d,         kh + row * 64 + g * 8);
            cp16(so + 8192 + d,  vh + row * 64 + g * 8);
            cp16(so + 16384 + d, vl + row * 64 + g * 8);
        }
    };

    // persistent Q fragments (hi + lo)
    uint32_t QAh[4][4], QAl[4][4];
    {
        const __half* qh = g_qh + base;
        const __half* ql = g_ql + base;
        const int r0 = qt * 64 + warp * 16 + r16;
        #pragma unroll
        for (int kc = 0; kc < 4; kc++) {
            int c0 = kc * 16 + 2 * t4;
            QAh[kc][0] = *(const uint32_t*)(qh + (long)r0      * 64 + c0);
            QAh[kc][1] = *(const uint32_t*)(qh + (long)(r0 + 8)* 64 + c0);
            QAh[kc][2] = *(const uint32_t*)(qh + (long)r0      * 64 + c0 + 8);
            QAh[kc][3] = *(const uint32_t*)(qh + (long)(r0 + 8)* 64 + c0 + 8);
            QAl[kc][0] = *(const uint32_t*)(ql + (long)r0      * 64 + c0);
            QAl[kc][1] = *(const uint32_t*)(ql + (long)(r0 + 8)* 64 + c0);
            QAl[kc][2] = *(const uint32_t*)(ql + (long)r0      * 64 + c0 + 8);
            QAl[kc][3] = *(const uint32_t*)(ql + (long)(r0 + 8)* 64 + c0 + 8);
        }
    }

    float O[8][4];
    #pragma unroll
    for (int j = 0; j < 8; j++)
        #pragma unroll
        for (int c = 0; c < 4; c++) O[j][c] = 0.f;
    float mrow[2] = {-1e30f, -1e30f};
    float lrow[2] = {0.f, 0.f};

    load_kv(0, 0);
    cp_commit();

    for (int kt = 0; kt < NT; kt++) {
        const int st = kt & 1;
        const uint32_t so = aS + (uint32_t)st * ASTG;
        if (kt + 1 < NT) {
            load_kv(kt + 1, st ^ 1);
            cp_commit();
            cp_wait<1>();
        } else {
            cp_wait<0>();
        }
        __syncthreads();

        // ---- S = (Qh + Ql) Kh^T ----
        float S[8][4];
        #pragma unroll
        for (int j = 0; j < 8; j++)
            #pragma unroll
            for (int c = 0; c < 4; c++) S[j][c] = 0.f;

        #pragma unroll
        for (int kc = 0; kc < 4; kc++) {
            #pragma unroll
            for (int j = 0; j < 8; j++) {
                uint32_t off = (uint32_t)((8 * j + rl) * 128 +
                                          (((2 * kc + sub) ^ rl) * 16)) + so;
                uint32_t b0, b1;
                ldsm_x2(b0, b1, off);
                mma16816(S[j], QAh[kc], b0, b1);
                mma16816(S[j], QAl[kc], b0, b1);
            }
        }

        // ---- online softmax (warp-local) ----
        #pragma unroll
        for (int hh = 0; hh < 2; hh++) {
            float mx = -1e30f;
            #pragma unroll
            for (int j = 0; j < 8; j++)
                mx = fmaxf(mx, fmaxf(S[j][2*hh], S[j][2*hh+1]));
            mx = fmaxf(mx, __shfl_xor_sync(0xffffffffu, mx, 1));
            mx = fmaxf(mx, __shfl_xor_sync(0xffffffffu, mx, 2));
            float mn   = fmaxf(mrow[hh], mx);
            float corr = __expf(mrow[hh] - mn);
            float sum = 0.f;
            #pragma unroll
            for (int j = 0; j < 8; j++) {
                S[j][2*hh]   = __expf(S[j][2*hh]   - mn);
                S[j][2*hh+1] = __expf(S[j][2*hh+1] - mn);
                sum += S[j][2*hh] + S[j][2*hh+1];
            }
            sum += __shfl_xor_sync(0xffffffffu, sum, 1);
            sum += __shfl_xor_sync(0xffffffffu, sum, 2);
            lrow[hh] = lrow[hh] * corr + sum;
            mrow[hh] = mn;
            #pragma unroll
            for (int j = 0; j < 8; j++) {
                O[j][2*hh]   *= corr;
                O[j][2*hh+1] *= corr;
            }
        }

        // ---- P (fp16, single plane): acc layout -> A-fragment layout ----
        uint32_t PA[4][4];
        #pragma unroll
        for (int nc = 0; nc < 4; nc++) {
            const float* s0 = S[2*nc];
            const float* s1 = S[2*nc+1];
            PA[nc][0] = cvt2_f16(s0[0], s0[1]);
            PA[nc][1] = cvt2_f16(s0[2], s0[3]);
            PA[nc][2] = cvt2_f16(s1[0], s1[1]);
            PA[nc][3] = cvt2_f16(s1[2], s1[3]);
        }

        // ---- O += P (Vh + Vl) ----
        #pragma unroll
        for (int nc = 0; nc < 4; nc++) {
            #pragma unroll
            for (int j = 0; j < 8; j++) {
                uint32_t off = (uint32_t)((16 * nc + (lane & 15)) * 128 +
                                          ((j ^ rl) * 16)) + so;
                uint32_t v0h, v1h, v0l, v1l;
                ldsm_x2_t(v0h, v1h, off + 8192);
                ldsm_x2_t(v0l, v1l, off + 16384);
                mma16816(O[j], PA[nc], v0h, v1h);
                mma16816(O[j], PA[nc], v0l, v1l);
            }
        }
        __syncthreads();   // stage reuse safety for next prefetch
    }

    // ---- epilogue: write fp16 attention output (single plane) ----
    {
        float inv0 = 1.0f / lrow[0];
        float inv1 = 1.0f / lrow[1];
        __half* ob = g_aoh + base;
        const int r0 = qt * 64 + warp * 16 + r16;
        #pragma unroll
        for (int j = 0; j < 8; j++) {
            int c = 8 * j + 2 * t4;
            *(uint32_t*)&ob[(long)r0      * 64 + c] =
                cvt2_f16(O[j][0] * inv0, O[j][1] * inv0);
            *(uint32_t*)&ob[(long)(r0 + 8)* 64 + c] =
                cvt2_f16(O[j][2] * inv1, O[j][3] * inv1);
        }
    }
}

// ---------------------------------------------------------------------------
// Kernel 3: unify GEMM, fp16 HMMA, 2 MMA terms: out = Ah * (Wh + Wl) + bu.
// Dynamic smem 48KB: stage st at st*24576: [Ah 8KB | Wh 8KB | Wl 8KB].
// grid=(16,128), block=128.
// ---------------------------------------------------------------------------
#define USTG 24576

__global__ __launch_bounds__(128) void unify_kernel(
    const float* __restrict__ bu,
    float* __restrict__ out)
{
    extern __shared__ __align__(16) char smem[];
    const uint32_t aS = smem_u32(smem);

    const int tid  = threadIdx.x;
    const int lane = tid & 31;
    const int warp = tid >> 5;
    const int row0 = blockIdx.y * 64;
    const int col0 = blockIdx.x * 64;
    const int b    = row0 >> 11;       // tiles never straddle b
    const int t0   = row0 & 2047;

    const int t4   = lane & 3;
    const int r16  = lane >> 2;
    const int rl   = lane & 7;
    const int sub  = (lane >> 3) & 1;
    const int half = (lane >> 3) & 1;
    const int kh   = (lane >> 4) & 1;

    auto load_tile = [&](int h, int st) {
        const __half* ga = g_aoh + ((long)(b * HH + h)) * TT * SD + (long)t0 * SD;
        const __half* gwh = g_wh + (long)col0 * EE + h * 64;
        const __half* gwl = g_wl + (long)col0 * EE + h * 64;
        const uint32_t so = aS + (uint32_t)st * USTG;
        #pragma unroll
        for (int it = 0; it < 4; it++) {
            int idx = it * 128 + tid;
            int row = idx >> 3, g = idx & 7;
            uint32_t d = (uint32_t)(row * 128 + ((g ^ (row & 7)) * 16));
            cp16(so + d,         ga  + row * 64 + g * 8);
            cp16(so + 8192 + d,  gwh + (long)row * EE + g * 8);
            cp16(so + 16384 + d, gwl + (long)row * EE + g * 8);
        }
    };

    float acc[8][4];
    #pragma unroll
    for (int j = 0; j < 8; j++)
        #pragma unroll
        for (int c = 0; c < 4; c++) acc[j][c] = 0.f;

    load_tile(0, 0);
    cp_commit();

    for (int h = 0; h < HH; h++) {
        const int st = h & 1;
        const uint32_t so = aS + (uint32_t)st * USTG;
        if (h + 1 < HH) {
            load_tile(h + 1, st ^ 1);
            cp_commit();
            cp_wait<1>();
        } else {
            cp_wait<0>();
        }
        __syncthreads();

        #pragma unroll
        for (int kc = 0; kc < 4; kc++) {
            int arow = warp * 16 + rl + 8 * half;
            uint32_t offA = (uint32_t)(arow * 128 +
                                       (((2 * kc + kh) ^ rl) * 16)) + so;
            uint32_t Ah[4];
            ldsm_x4(Ah, offA);
            #pragma unroll
            for (int j = 0; j < 8; j++) {
                uint32_t offW = (uint32_t)((8 * j + rl) * 128 +
                                           (((2 * kc + sub) ^ rl) * 16)) + so;
                uint32_t w0h, w1h, w0l, w1l;
                ldsm_x2(w0h, w1h, offW + 8192);
                ldsm_x2(w0l, w1l, offW + 16384);
                mma16816(acc[j], Ah, w0h, w1h);
                mma16816(acc[j], Ah, w0l, w1l);
            }
        }
        __syncthreads();
    }

    // store + bias
    {
        const int r0g = row0 + warp * 16 + r16;
        #pragma unroll
        for (int j = 0; j < 8; j++) {
            int c = col0 + 8 * j + 2 * t4;
            float2 bias = *(const float2*)&bu[c];
            float2 v0 = make_float2(acc[j][0] + bias.x, acc[j][1] + bias.y);
            float2 v1 = make_float2(acc[j][2] + bias.x, acc[j][3] + bias.y);
            *(float2*)&out[(long)r0g      * EE + c] = v0;
            *(float2*)&out[(long)(r0g + 8)* EE + c] = v1;
        }
    }
}

// ---------------------------------------------------------------------------
extern "C" void kernel_launch(void* const* d_in, const int* in_sizes, int n_in,
                              void* d_out, int out_size)
{
    const float* x  = (const float*)d_in[0];
    const float* Wk = (const float*)d_in[1];
    const float* Wq = (const float*)d_in[2];
    const float* Wv = (const float*)d_in[3];
    const float* Wu = (const float*)d_in[4];
    const float* bu = (const float*)d_in[5];
    float* out = (float*)d_out;

    cudaFuncSetAttribute(attn_kernel,
                         cudaFuncAttributeMaxDynamicSharedMemorySize, 49152);
    cudaFuncSetAttribute(unify_kernel,
                         cudaFuncAttributeMaxDynamicSharedMemorySize, 49152);

    wprep_kernel<<<(EE * EE / 4) / 256, 256>>>(Wu);
    qkv_kernel<<<NROWS / 64, 256>>>(x, Wk, Wq, Wv);
    attn_kernel<<<dim3(TT / 64, BB * HH), 128, 49152>>>();
    unify_kernel<<<dim3(EE / 64, (BB * TT) / 64), 128, 49152>>>(bu, out);
}

// round 10
// speedup vs baseline: 1.8555x; 1.1949x over previous
#include <cuda_runtime.h>
#include <cuda_fp16.h>
#include <cstdint>

// Problem constants
#define BB   4
#define TT   2048
#define HH   16
#define SD   64
#define EE   1024
#define NROWS (BB*TT*HH)               // 131072 rows of 64
#define QK_SCALE 0.17677669529663687f  // 1 / 1024^0.25

// Scratch (device globals — no allocation allowed), fp16 formats:
//   q: hi + lo residual (2-term)   k: single   v: single
//   ao: single                     Wu: single
__device__ __align__(16) __half g_qh[NROWS*SD], g_ql[NROWS*SD];
__device__ __align__(16) __half g_kh[NROWS*SD];
__device__ __align__(16) __half g_vh[NROWS*SD];
__device__ __align__(16) __half g_aoh[NROWS*SD];
__device__ __align__(16) __half g_wh[EE*EE];

// ---------------------------------------------------------------------------
// helpers
// ---------------------------------------------------------------------------
__device__ __forceinline__ uint32_t smem_u32(const void* p) {
    return (uint32_t)__cvta_generic_to_shared(p);
}
__device__ __forceinline__ void ldsm_x2(uint32_t& r0, uint32_t& r1, uint32_t a) {
    asm volatile("ldmatrix.sync.aligned.m8n8.x2.shared.b16 {%0,%1},[%2];"
                 : "=r"(r0), "=r"(r1) : "r"(a));
}
__device__ __forceinline__ void ldsm_x2_t(uint32_t& r0, uint32_t& r1, uint32_t a) {
    asm volatile("ldmatrix.sync.aligned.m8n8.x2.trans.shared.b16 {%0,%1},[%2];"
                 : "=r"(r0), "=r"(r1) : "r"(a));
}
__device__ __forceinline__ void ldsm_x4(uint32_t* r, uint32_t a) {
    asm volatile("ldmatrix.sync.aligned.m8n8.x4.shared.b16 {%0,%1,%2,%3},[%4];"
                 : "=r"(r[0]), "=r"(r[1]), "=r"(r[2]), "=r"(r[3]) : "r"(a));
}
// D += A * B (m16n8k16, fp16 in, f32 accum)
__device__ __forceinline__ void mma16816(float* d, const uint32_t* a,
                                         uint32_t b0, uint32_t b1) {
    asm volatile("mma.sync.aligned.m16n8k16.row.col.f32.f16.f16.f32 "
                 "{%0,%1,%2,%3},{%4,%5,%6,%7},{%8,%9},{%0,%1,%2,%3};"
                 : "+f"(d[0]), "+f"(d[1]), "+f"(d[2]), "+f"(d[3])
                 : "r"(a[0]), "r"(a[1]), "r"(a[2]), "r"(a[3]), "r"(b0), "r"(b1));
}
__device__ __forceinline__ uint32_t cvt2_f16(float x, float y) {
    __half2 h = __floats2half2_rn(x, y);
    return *reinterpret_cast<uint32_t*>(&h);
}
__device__ __forceinline__ uint32_t cvt2_f16_lo(float x, float y, uint32_t hi) {
    __half2 h = *reinterpret_cast<__half2*>(&hi);
    return cvt2_f16(x - __low2float(h), y - __high2float(h));
}
__device__ __forceinline__ void cp16(uint32_t dst, const void* src) {
    asm volatile("cp.async.cg.shared.global [%0], [%1], 16;"
                 :: "r"(dst), "l"(src));
}
__device__ __forceinline__ void cp_commit() {
    asm volatile("cp.async.commit_group;");
}
template <int N> __device__ __forceinline__ void cp_wait() {
    asm volatile("cp.async.wait_group %0;" :: "n"(N));
}

// ---------------------------------------------------------------------------
// Kernel 0: convert Wu -> fp16 (single plane, once)
// ---------------------------------------------------------------------------
__global__ __launch_bounds__(256) void wprep_kernel(const float* __restrict__ Wu)
{
    int i = blockIdx.x * 256 + threadIdx.x;     // one float4 each
    float4 v = ((const float4*)Wu)[i];
    ((uint2*)g_wh)[i] = make_uint2(cvt2_f16(v.x, v.y), cvt2_f16(v.z, v.w));
}

// ---------------------------------------------------------------------------
// Kernel 1: QKV projections (fp32 SIMT, at FFMA roofline).
// x is [b,t,h,s] flat [131072][64]. Emits fp16 q(hi,lo), k, v in [b,h,t,s].
// ---------------------------------------------------------------------------
#define SWZ4(r, c4) (((r) << 4) + ((c4) ^ (((r) >> 2) & 15)))
#define DOT4(acc, A, W) \
    acc += (A).x * (W).x + (A).y * (W).y + (A).z * (W).z + (A).w * (W).w;

__global__ __launch_bounds__(256) void qkv_kernel(
    const float* __restrict__ x,
    const float* __restrict__ Wk,
    const float* __restrict__ Wq,
    const float* __restrict__ Wv)
{
    __shared__ float4 Xs[64 * 16];
    __shared__ float4 Ws[64 * 16];

    const int tid = threadIdx.x;
    const int ty = tid >> 4;
    const int tx = tid & 15;
    const int row0 = blockIdx.x * 64;

    const float4* xg = (const float4*)(x + (long)row0 * 64);
    #pragma unroll
    for (int i = 0; i < 4; i++) Xs[tid + 256 * i] = xg[tid + 256 * i];

    const float* Wlist[3] = {Wq, Wk, Wv};
    const float  scl [3]  = {QK_SCALE, QK_SCALE, 1.0f};
    __half* outh[3] = {g_qh, g_kh, g_vh};

    for (int mm = 0; mm < 3; mm++) {
        __syncthreads();
        const float4* Wg = (const float4*)Wlist[mm];
        #pragma unroll
        for (int ii = 0; ii < 4; ii++) {
            int i = tid + 256 * ii;
            Ws[SWZ4(i >> 4, i & 15)] = Wg[i];
        }
        __syncthreads();

        float acc[4][4];
        #pragma unroll
        for (int i = 0; i < 4; i++)
            #pragma unroll
            for (int j = 0; j < 4; j++) acc[i][j] = 0.f;

        #pragma unroll 4
        for (int k4 = 0; k4 < 16; k4++) {
            float4 a[4], w[4];
            #pragma unroll
            for (int i = 0; i < 4; i++) a[i] = Xs[(ty * 4 + i) * 16 + k4];
            #pragma unroll
            for (int j = 0; j < 4; j++) w[j] = Ws[(tx * 4 + j) * 16 + (k4 ^ tx)];
            #pragma unroll
            for (int i = 0; i < 4; i++)
                #pragma unroll
                for (int j = 0; j < 4; j++)
                    DOT4(acc[i][j], a[i], w[j]);
        }

        const float s = scl[mm];
        __half* oh = outh[mm];
        #pragma unroll
        for (int i = 0; i < 4; i++) {
            int r = row0 + ty * 4 + i;            // (b,t,h) flattened
            int b = r >> 15;
            int t = (r >> 4) & 2047;
            int h = r & 15;
            long obase = (((long)(b * HH + h)) * TT + t) * SD + tx * 4;
            float y0 = acc[i][0] * s, y1 = acc[i][1] * s;
            float y2 = acc[i][2] * s, y3 = acc[i][3] * s;
            uint32_t h01 = cvt2_f16(y0, y1), h23 = cvt2_f16(y2, y3);
            *(uint32_t*)&oh[obase]     = h01;
            *(uint32_t*)&oh[obase + 2] = h23;
            if (mm == 0) {   // q lo residual plane
                *(uint32_t*)&g_ql[obase]     = cvt2_f16_lo(y0, y1, h01);
                *(uint32_t*)&g_ql[obase + 2] = cvt2_f16_lo(y2, y3, h23);
            }
        }
    }
}

// ---------------------------------------------------------------------------
// Kernel 2: flash attention, fp16 HMMA.
//   S = (qh + ql) * kh   (2 MMA terms)
//   O += Ph * vh         (1 MMA term)
// grid=(T/64, B*H), block=128. Dynamic smem 32KB:
// stage st at st*16384: [Kh 8KB | Vh 8KB]. cp.async double-buffered.
// ---------------------------------------------------------------------------
#define NT (TT / 64)
#define ASTG 16384

__global__ __launch_bounds__(128) void attn_kernel()
{
    extern __shared__ __align__(16) char smem[];
    const uint32_t aS = smem_u32(smem);

    const int tid  = threadIdx.x;
    const int lane = tid & 31;
    const int warp = tid >> 5;
    const int qt   = blockIdx.x;
    const int bh   = blockIdx.y;
    const long base = (long)bh * TT * SD;

    const int t4  = lane & 3;
    const int r16 = lane >> 2;
    const int rl  = lane & 7;
    const int sub = (lane >> 3) & 1;

    auto load_kv = [&](int kt, int st) {
        const __half* kh = g_kh + base + kt * 4096;
        const __half* vh = g_vh + base + kt * 4096;
        const uint32_t so = aS + (uint32_t)st * ASTG;
        #pragma unroll
        for (int it = 0; it < 4; it++) {
            int idx = it * 128 + tid;
            int row = idx >> 3, g = idx & 7;
            uint32_t d = (uint32_t)(row * 128 + ((g ^ (row & 7)) * 16));
            cp16(so + d,        kh + row * 64 + g * 8);
            cp16(so + 8192 + d, vh + row * 64 + g * 8);
        }
    };

    // persistent Q fragments (hi + lo)
    uint32_t QAh[4][4], QAl[4][4];
    {
        const __half* qh = g_qh + base;
        const __half* ql = g_ql + base;
        const int r0 = qt * 64 + warp * 16 + r16;
        #pragma unroll
        for (int kc = 0; kc < 4; kc++) {
            int c0 = kc * 16 + 2 * t4;
            QAh[kc][0] = *(const uint32_t*)(qh + (long)r0      * 64 + c0);
            QAh[kc][1] = *(const uint32_t*)(qh + (long)(r0 + 8)* 64 + c0);
            QAh[kc][2] = *(const uint32_t*)(qh + (long)r0      * 64 + c0 + 8);
            QAh[kc][3] = *(const uint32_t*)(qh + (long)(r0 + 8)* 64 + c0 + 8);
            QAl[kc][0] = *(const uint32_t*)(ql + (long)r0      * 64 + c0);
            QAl[kc][1] = *(const uint32_t*)(ql + (long)(r0 + 8)* 64 + c0);
            QAl[kc][2] = *(const uint32_t*)(ql + (long)r0      * 64 + c0 + 8);
            QAl[kc][3] = *(const uint32_t*)(ql + (long)(r0 + 8)* 64 + c0 + 8);
        }
    }

    float O[8][4];
    #pragma unroll
    for (int j = 0; j < 8; j++)
        #pragma unroll
        for (int c = 0; c < 4; c++) O[j][c] = 0.f;
    float mrow[2] = {-1e30f, -1e30f};
    float lrow[2] = {0.f, 0.f};

    load_kv(0, 0);
    cp_commit();

    for (int kt = 0; kt < NT; kt++) {
        const int st = kt & 1;
        const uint32_t so = aS + (uint32_t)st * ASTG;
        if (kt + 1 < NT) {
            load_kv(kt + 1, st ^ 1);
            cp_commit();
            cp_wait<1>();
        } else {
            cp_wait<0>();
        }
        __syncthreads();

        // ---- S = (Qh + Ql) Kh^T ----
        float S[8][4];
        #pragma unroll
        for (int j = 0; j < 8; j++)
            #pragma unroll
            for (int c = 0; c < 4; c++) S[j][c] = 0.f;

        #pragma unroll
        for (int kc = 0; kc < 4; kc++) {
            #pragma unroll
            for (int j = 0; j < 8; j++) {
                uint32_t off = (uint32_t)((8 * j + rl) * 128 +
                                          (((2 * kc + sub) ^ rl) * 16)) + so;
                uint32_t b0, b1;
                ldsm_x2(b0, b1, off);
                mma16816(S[j], QAh[kc], b0, b1);
                mma16816(S[j], QAl[kc], b0, b1);
            }
        }

        // ---- online softmax (warp-local) ----
        #pragma unroll
        for (int hh = 0; hh < 2; hh++) {
            float mx = -1e30f;
            #pragma unroll
            for (int j = 0; j < 8; j++)
                mx = fmaxf(mx, fmaxf(S[j][2*hh], S[j][2*hh+1]));
            mx = fmaxf(mx, __shfl_xor_sync(0xffffffffu, mx, 1));
            mx = fmaxf(mx, __shfl_xor_sync(0xffffffffu, mx, 2));
            float mn   = fmaxf(mrow[hh], mx);
            float corr = __expf(mrow[hh] - mn);
            float sum = 0.f;
            #pragma unroll
            for (int j = 0; j < 8; j++) {
                S[j][2*hh]   = __expf(S[j][2*hh]   - mn);
                S[j][2*hh+1] = __expf(S[j][2*hh+1] - mn);
                sum += S[j][2*hh] + S[j][2*hh+1];
            }
            sum += __shfl_xor_sync(0xffffffffu, sum, 1);
            sum += __shfl_xor_sync(0xffffffffu, sum, 2);
            lrow[hh] = lrow[hh] * corr + sum;
            mrow[hh] = mn;
            #pragma unroll
            for (int j = 0; j < 8; j++) {
                O[j][2*hh]   *= corr;
                O[j][2*hh+1] *= corr;
            }
        }

        // ---- P (fp16): acc layout -> A-fragment layout ----
        uint32_t PA[4][4];
        #pragma unroll
        for (int nc = 0; nc < 4; nc++) {
            const float* s0 = S[2*nc];
            const float* s1 = S[2*nc+1];
            PA[nc][0] = cvt2_f16(s0[0], s0[1]);
            PA[nc][1] = cvt2_f16(s0[2], s0[3]);
            PA[nc][2] = cvt2_f16(s1[0], s1[1]);
            PA[nc][3] = cvt2_f16(s1[2], s1[3]);
        }

        // ---- O += P Vh ----
        #pragma unroll
        for (int nc = 0; nc < 4; nc++) {
            #pragma unroll
            for (int j = 0; j < 8; j++) {
                uint32_t off = (uint32_t)((16 * nc + (lane & 15)) * 128 +
                                          ((j ^ rl) * 16)) + so;
                uint32_t v0, v1;
                ldsm_x2_t(v0, v1, off + 8192);
                mma16816(O[j], PA[nc], v0, v1);
            }
        }
        __syncthreads();   // stage reuse safety for next prefetch
    }

    // ---- epilogue: write fp16 attention output ----
    {
        float inv0 = 1.0f / lrow[0];
        float inv1 = 1.0f / lrow[1];
        __half* ob = g_aoh + base;
        const int r0 = qt * 64 + warp * 16 + r16;
        #pragma unroll
        for (int j = 0; j < 8; j++) {
            int c = 8 * j + 2 * t4;
            *(uint32_t*)&ob[(long)r0      * 64 + c] =
                cvt2_f16(O[j][0] * inv0, O[j][1] * inv0);
            *(uint32_t*)&ob[(long)(r0 + 8)* 64 + c] =
                cvt2_f16(O[j][2] * inv1, O[j][3] * inv1);
        }
    }
}

// ---------------------------------------------------------------------------
// Kernel 3: unify GEMM, fp16 HMMA, single term, W shared by 8 warps.
// Block = 256 threads (8 warps) covering 128 rows x 64 cols; warp w owns
// rows w*16..w*16+15. Dynamic smem 48KB: stage st at st*24576:
//   [A 16KB (128 rows x 64) | W 8KB (64 rows x 64)].
// grid=(EE/64, B*T/128) = (16, 64).
// ---------------------------------------------------------------------------
#define USTG 24576

__global__ __launch_bounds__(256) void unify_kernel(
    const float* __restrict__ bu,
    float* __restrict__ out)
{
    extern __shared__ __align__(16) char smem[];
    const uint32_t aS = smem_u32(smem);

    const int tid  = threadIdx.x;
    const int lane = tid & 31;
    const int warp = tid >> 5;
    const int row0 = blockIdx.y * 128;
    const int col0 = blockIdx.x * 64;
    const int b    = row0 >> 11;       // tiles never straddle b
    const int t0   = row0 & 2047;

    const int t4   = lane & 3;
    const int r16  = lane >> 2;
    const int rl   = lane & 7;
    const int sub  = (lane >> 3) & 1;
    const int half = (lane >> 3) & 1;
    const int kh   = (lane >> 4) & 1;

    auto load_tile = [&](int h, int st) {
        const __half* ga = g_aoh + ((long)(b * HH + h)) * TT * SD + (long)t0 * SD;
        const __half* gw = g_wh + (long)col0 * EE + h * 64;
        const uint32_t so = aS + (uint32_t)st * USTG;
        // A: 128 rows x 64 cols = 1024 granules of 16B; 256 threads x 4
        #pragma unroll
        for (int it = 0; it < 4; it++) {
            int idx = it * 256 + tid;
            int row = idx >> 3, g = idx & 7;
            uint32_t d = (uint32_t)(row * 128 + ((g ^ (row & 7)) * 16));
            cp16(so + d, ga + row * 64 + g * 8);
        }
        // W: 64 rows x 64 cols = 512 granules; 256 threads x 2
        #pragma unroll
        for (int it = 0; it < 2; it++) {
            int idx = it * 256 + tid;
            int row = idx >> 3, g = idx & 7;
            uint32_t d = (uint32_t)(row * 128 + ((g ^ (row & 7)) * 16));
            cp16(so + 16384 + d, gw + (long)row * EE + g * 8);
        }
    };

    float acc[8][4];
    #pragma unroll
    for (int j = 0; j < 8; j++)
        #pragma unroll
        for (int c = 0; c < 4; c++) acc[j][c] = 0.f;

    load_tile(0, 0);
    cp_commit();

    for (int h = 0; h < HH; h++) {
        const int st = h & 1;
        const uint32_t so = aS + (uint32_t)st * USTG;
        if (h + 1 < HH) {
            load_tile(h + 1, st ^ 1);
            cp_commit();
            cp_wait<1>();
        } else {
            cp_wait<0>();
        }
        __syncthreads();

        #pragma unroll
        for (int kc = 0; kc < 4; kc++) {
            int arow = warp * 16 + rl + 8 * half;
            uint32_t offA = (uint32_t)(arow * 128 +
                                       (((2 * kc + kh) ^ rl) * 16)) + so;
            uint32_t Ah[4];
            ldsm_x4(Ah, offA);
            #pragma unroll
            for (int j = 0; j < 8; j++) {
                uint32_t offW = (uint32_t)((8 * j + rl) * 128 +
                                           (((2 * kc + sub) ^ rl) * 16)) + so + 16384;
                uint32_t w0, w1;
                ldsm_x2(w0, w1, offW);
                mma16816(acc[j], Ah, w0, w1);
            }
        }
        __syncthreads();
    }

    // store + bias
    {
        const int r0g = row0 + warp * 16 + r16;
        #pragma unroll
        for (int j = 0; j < 8; j++) {
            int c = col0 + 8 * j + 2 * t4;
            float2 bias = *(const float2*)&bu[c];
            float2 v0 = make_float2(acc[j][0] + bias.x, acc[j][1] + bias.y);
            float2 v1 = make_float2(acc[j][2] + bias.x, acc[j][3] + bias.y);
            *(float2*)&out[(long)r0g      * EE + c] = v0;
            *(float2*)&out[(long)(r0g + 8)* EE + c] = v1;
        }
    }
}

// ---------------------------------------------------------------------------
extern "C" void kernel_launch(void* const* d_in, const int* in_sizes, int n_in,
                              void* d_out, int out_size)
{
    const float* x  = (const float*)d_in[0];
    const float* Wk = (const float*)d_in[1];
    const float* Wq = (const float*)d_in[2];
    const float* Wv = (const float*)d_in[3];
    const float* Wu = (const float*)d_in[4];
    const float* bu = (const float*)d_in[5];
    float* out = (float*)d_out;

    cudaFuncSetAttribute(attn_kernel,
                         cudaFuncAttributeMaxDynamicSharedMemorySize, 32768);
    cudaFuncSetAttribute(unify_kernel,
                         cudaFuncAttributeMaxDynamicSharedMemorySize, 49152);

    wprep_kernel<<<(EE * EE / 4) / 256, 256>>>(Wu);
    qkv_kernel<<<NROWS / 64, 256>>>(x, Wk, Wq, Wv);
    attn_kernel<<<dim3(TT / 64, BB * HH), 128, 32768>>>();
    unify_kernel<<<dim3(EE / 64, (BB * TT) / 128), 256, 49152>>>(bu, out);
}

// round 11
// speedup vs baseline: 2.5660x; 1.3829x over previous
#include <cuda_runtime.h>
#include <cuda_fp16.h>
#include <cstdint>

// Problem constants
#define BB   4
#define TT   2048
#define HH   16
#define SD   64
#define EE   1024
#define NROWS (BB*TT*HH)               // 131072 rows of 64
#define QK_SCALE 0.17677669529663687f  // 1 / 1024^0.25

// Scratch (device globals — no allocation allowed), all single-plane fp16
__device__ __align__(16) __half g_qh[NROWS*SD];
__device__ __align__(16) __half g_kh[NROWS*SD];
__device__ __align__(16) __half g_vh[NROWS*SD];
__device__ __align__(16) __half g_aoh[NROWS*SD];
__device__ __align__(16) __half g_wh[EE*EE];

// ---------------------------------------------------------------------------
// helpers
// ---------------------------------------------------------------------------
__device__ __forceinline__ uint32_t smem_u32(const void* p) {
    return (uint32_t)__cvta_generic_to_shared(p);
}
__device__ __forceinline__ void ldsm_x2(uint32_t& r0, uint32_t& r1, uint32_t a) {
    asm volatile("ldmatrix.sync.aligned.m8n8.x2.shared.b16 {%0,%1},[%2];"
                 : "=r"(r0), "=r"(r1) : "r"(a));
}
__device__ __forceinline__ void ldsm_x2_t(uint32_t& r0, uint32_t& r1, uint32_t a) {
    asm volatile("ldmatrix.sync.aligned.m8n8.x2.trans.shared.b16 {%0,%1},[%2];"
                 : "=r"(r0), "=r"(r1) : "r"(a));
}
__device__ __forceinline__ void ldsm_x4(uint32_t* r, uint32_t a) {
    asm volatile("ldmatrix.sync.aligned.m8n8.x4.shared.b16 {%0,%1,%2,%3},[%4];"
                 : "=r"(r[0]), "=r"(r[1]), "=r"(r[2]), "=r"(r[3]) : "r"(a));
}
// D += A * B (m16n8k16, fp16 in, f32 accum)
__device__ __forceinline__ void mma16816(float* d, const uint32_t* a,
                                         uint32_t b0, uint32_t b1) {
    asm volatile("mma.sync.aligned.m16n8k16.row.col.f32.f16.f16.f32 "
                 "{%0,%1,%2,%3},{%4,%5,%6,%7},{%8,%9},{%0,%1,%2,%3};"
                 : "+f"(d[0]), "+f"(d[1]), "+f"(d[2]), "+f"(d[3])
                 : "r"(a[0]), "r"(a[1]), "r"(a[2]), "r"(a[3]), "r"(b0), "r"(b1));
}
__device__ __forceinline__ uint32_t cvt2_f16(float x, float y) {
    __half2 h = __floats2half2_rn(x, y);
    return *reinterpret_cast<uint32_t*>(&h);
}
__device__ __forceinline__ void cp16(uint32_t dst, const void* src) {
    asm volatile("cp.async.cg.shared.global [%0], [%1], 16;"
                 :: "r"(dst), "l"(src));
}
__device__ __forceinline__ void cp_commit() {
    asm volatile("cp.async.commit_group;");
}
template <int N> __device__ __forceinline__ void cp_wait() {
    asm volatile("cp.async.wait_group %0;" :: "n"(N));
}

// ---------------------------------------------------------------------------
// Kernel 0: convert Wu -> fp16 (once)
// ---------------------------------------------------------------------------
__global__ __launch_bounds__(256) void wprep_kernel(const float* __restrict__ Wu)
{
    int i = blockIdx.x * 256 + threadIdx.x;     // one float4 each
    float4 v = ((const float4*)Wu)[i];
    ((uint2*)g_wh)[i] = make_uint2(cvt2_f16(v.x, v.y), cvt2_f16(v.z, v.w));
}

// ---------------------------------------------------------------------------
// Kernel 1: QKV projections (fp32 SIMT, at FFMA roofline).
// x is [b,t,h,s] flat [131072][64]. Emits fp16 q, k, v in [b,h,t,s].
// ---------------------------------------------------------------------------
#define SWZ4(r, c4) (((r) << 4) + ((c4) ^ (((r) >> 2) & 15)))
#define DOT4(acc, A, W) \
    acc += (A).x * (W).x + (A).y * (W).y + (A).z * (W).z + (A).w * (W).w;

__global__ __launch_bounds__(256) void qkv_kernel(
    const float* __restrict__ x,
    const float* __restrict__ Wk,
    const float* __restrict__ Wq,
    const float* __restrict__ Wv)
{
    __shared__ float4 Xs[64 * 16];
    __shared__ float4 Ws[64 * 16];

    const int tid = threadIdx.x;
    const int ty = tid >> 4;
    const int tx = tid & 15;
    const int row0 = blockIdx.x * 64;

    const float4* xg = (const float4*)(x + (long)row0 * 64);
    #pragma unroll
    for (int i = 0; i < 4; i++) Xs[tid + 256 * i] = xg[tid + 256 * i];

    const float* Wlist[3] = {Wq, Wk, Wv};
    const float  scl [3]  = {QK_SCALE, QK_SCALE, 1.0f};
    __half* outh[3] = {g_qh, g_kh, g_vh};

    for (int mm = 0; mm < 3; mm++) {
        __syncthreads();
        const float4* Wg = (const float4*)Wlist[mm];
        #pragma unroll
        for (int ii = 0; ii < 4; ii++) {
            int i = tid + 256 * ii;
            Ws[SWZ4(i >> 4, i & 15)] = Wg[i];
        }
        __syncthreads();

        float acc[4][4];
        #pragma unroll
        for (int i = 0; i < 4; i++)
            #pragma unroll
            for (int j = 0; j < 4; j++) acc[i][j] = 0.f;

        #pragma unroll 4
        for (int k4 = 0; k4 < 16; k4++) {
            float4 a[4], w[4];
            #pragma unroll
            for (int i = 0; i < 4; i++) a[i] = Xs[(ty * 4 + i) * 16 + k4];
            #pragma unroll
            for (int j = 0; j < 4; j++) w[j] = Ws[(tx * 4 + j) * 16 + (k4 ^ tx)];
            #pragma unroll
            for (int i = 0; i < 4; i++)
                #pragma unroll
                for (int j = 0; j < 4; j++)
                    DOT4(acc[i][j], a[i], w[j]);
        }

        const float s = scl[mm];
        __half* oh = outh[mm];
        #pragma unroll
        for (int i = 0; i < 4; i++) {
            int r = row0 + ty * 4 + i;            // (b,t,h) flattened
            int b = r >> 15;
            int t = (r >> 4) & 2047;
            int h = r & 15;
            long obase = (((long)(b * HH + h)) * TT + t) * SD + tx * 4;
            *(uint32_t*)&oh[obase]     = cvt2_f16(acc[i][0] * s, acc[i][1] * s);
            *(uint32_t*)&oh[obase + 2] = cvt2_f16(acc[i][2] * s, acc[i][3] * s);
        }
    }
}

// ---------------------------------------------------------------------------
// Kernel 2: flash attention, fp16 HMMA, single-term QK and PV.
// grid=(T/128, B*H), block=128 (4 warps). Warp owns 32 q-rows: two m16
// row-groups -> every K/V fragment feeds 2 MMAs. Dynamic smem 32KB:
// stage st at st*16384: [Kh 8KB | Vh 8KB]. cp.async double-buffered.
// ---------------------------------------------------------------------------
#define NT (TT / 64)
#define ASTG 16384

__global__ __launch_bounds__(128) void attn_kernel()
{
    extern __shared__ __align__(16) char smem[];
    const uint32_t aS = smem_u32(smem);

    const int tid  = threadIdx.x;
    const int lane = tid & 31;
    const int warp = tid >> 5;
    const int qt   = blockIdx.x;
    const int bh   = blockIdx.y;
    const long base = (long)bh * TT * SD;

    const int t4  = lane & 3;
    const int r16 = lane >> 2;
    const int rl  = lane & 7;
    const int sub = (lane >> 3) & 1;

    auto load_kv = [&](int kt, int st) {
        const __half* kh = g_kh + base + kt * 4096;
        const __half* vh = g_vh + base + kt * 4096;
        const uint32_t so = aS + (uint32_t)st * ASTG;
        #pragma unroll
        for (int it = 0; it < 4; it++) {
            int idx = it * 128 + tid;
            int row = idx >> 3, g = idx & 7;
            uint32_t d = (uint32_t)(row * 128 + ((g ^ (row & 7)) * 16));
            cp16(so + d,        kh + row * 64 + g * 8);
            cp16(so + 8192 + d, vh + row * 64 + g * 8);
        }
    };

    // persistent Q fragments: rows r0..r0+15 (QA0) and r0+16..r0+31 (QA1)
    uint32_t QA0[4][4], QA1[4][4];
    {
        const __half* qh = g_qh + base;
        const int r0 = qt * 128 + warp * 32 + r16;
        #pragma unroll
        for (int kc = 0; kc < 4; kc++) {
            int c0 = kc * 16 + 2 * t4;
            QA0[kc][0] = *(const uint32_t*)(qh + (long)r0       * 64 + c0);
            QA0[kc][1] = *(const uint32_t*)(qh + (long)(r0 + 8) * 64 + c0);
            QA0[kc][2] = *(const uint32_t*)(qh + (long)r0       * 64 + c0 + 8);
            QA0[kc][3] = *(const uint32_t*)(qh + (long)(r0 + 8) * 64 + c0 + 8);
            QA1[kc][0] = *(const uint32_t*)(qh + (long)(r0 + 16)* 64 + c0);
            QA1[kc][1] = *(const uint32_t*)(qh + (long)(r0 + 24)* 64 + c0);
            QA1[kc][2] = *(const uint32_t*)(qh + (long)(r0 + 16)* 64 + c0 + 8);
            QA1[kc][3] = *(const uint32_t*)(qh + (long)(r0 + 24)* 64 + c0 + 8);
        }
    }

    float O0[8][4], O1[8][4];
    #pragma unroll
    for (int j = 0; j < 8; j++)
        #pragma unroll
        for (int c = 0; c < 4; c++) { O0[j][c] = 0.f; O1[j][c] = 0.f; }
    float mrow[4] = {-1e30f, -1e30f, -1e30f, -1e30f};
    float lrow[4] = {0.f, 0.f, 0.f, 0.f};

    load_kv(0, 0);
    cp_commit();

    for (int kt = 0; kt < NT; kt++) {
        const int st = kt & 1;
        const uint32_t so = aS + (uint32_t)st * ASTG;
        if (kt + 1 < NT) {
            load_kv(kt + 1, st ^ 1);
            cp_commit();
            cp_wait<1>();
        } else {
            cp_wait<0>();
        }
        __syncthreads();

        // ---- S = Q Kh^T (each K fragment feeds both row groups) ----
        float S0[8][4], S1[8][4];
        #pragma unroll
        for (int j = 0; j < 8; j++)
            #pragma unroll
            for (int c = 0; c < 4; c++) { S0[j][c] = 0.f; S1[j][c] = 0.f; }

        #pragma unroll
        for (int kc = 0; kc < 4; kc++) {
            #pragma unroll
            for (int j = 0; j < 8; j++) {
                uint32_t off = (uint32_t)((8 * j + rl) * 128 +
                                          (((2 * kc + sub) ^ rl) * 16)) + so;
                uint32_t b0, b1;
                ldsm_x2(b0, b1, off);
                mma16816(S0[j], QA0[kc], b0, b1);
                mma16816(S1[j], QA1[kc], b0, b1);
            }
        }

        // ---- online softmax (warp-local), 4 (group, row-half) states ----
        #pragma unroll
        for (int g = 0; g < 2; g++) {
            float (*S)[4] = g ? S1 : S0;
            float (*O)[4] = g ? O1 : O0;
            #pragma unroll
            for (int hh = 0; hh < 2; hh++) {
                int si = g * 2 + hh;
                float mx = -1e30f;
                #pragma unroll
                for (int j = 0; j < 8; j++)
                    mx = fmaxf(mx, fmaxf(S[j][2*hh], S[j][2*hh+1]));
                mx = fmaxf(mx, __shfl_xor_sync(0xffffffffu, mx, 1));
                mx = fmaxf(mx, __shfl_xor_sync(0xffffffffu, mx, 2));
                float mn   = fmaxf(mrow[si], mx);
                float corr = __expf(mrow[si] - mn);
                float sum = 0.f;
                #pragma unroll
                for (int j = 0; j < 8; j++) {
                    S[j][2*hh]   = __expf(S[j][2*hh]   - mn);
                    S[j][2*hh+1] = __expf(S[j][2*hh+1] - mn);
                    sum += S[j][2*hh] + S[j][2*hh+1];
                }
                sum += __shfl_xor_sync(0xffffffffu, sum, 1);
                sum += __shfl_xor_sync(0xffffffffu, sum, 2);
                lrow[si] = lrow[si] * corr + sum;
                mrow[si] = mn;
                #pragma unroll
                for (int j = 0; j < 8; j++) {
                    O[j][2*hh]   *= corr;
                    O[j][2*hh+1] *= corr;
                }
            }
        }

        // ---- P (fp16): acc layout -> A-fragment layout ----
        uint32_t PA0[4][4], PA1[4][4];
        #pragma unroll
        for (int nc = 0; nc < 4; nc++) {
            PA0[nc][0] = cvt2_f16(S0[2*nc][0],   S0[2*nc][1]);
            PA0[nc][1] = cvt2_f16(S0[2*nc][2],   S0[2*nc][3]);
            PA0[nc][2] = cvt2_f16(S0[2*nc+1][0], S0[2*nc+1][1]);
            PA0[nc][3] = cvt2_f16(S0[2*nc+1][2], S0[2*nc+1][3]);
            PA1[nc][0] = cvt2_f16(S1[2*nc][0],   S1[2*nc][1]);
            PA1[nc][1] = cvt2_f16(S1[2*nc][2],   S1[2*nc][3]);
            PA1[nc][2] = cvt2_f16(S1[2*nc+1][0], S1[2*nc+1][1]);
            PA1[nc][3] = cvt2_f16(S1[2*nc+1][2], S1[2*nc+1][3]);
        }

        // ---- O += P Vh (each V fragment feeds both row groups) ----
        #pragma unroll
        for (int nc = 0; nc < 4; nc++) {
            #pragma unroll
            for (int j = 0; j < 8; j++) {
                uint32_t off = (uint32_t)((16 * nc + (lane & 15)) * 128 +
                                          ((j ^ rl) * 16)) + so;
                uint32_t v0, v1;
                ldsm_x2_t(v0, v1, off + 8192);
                mma16816(O0[j], PA0[nc], v0, v1);
                mma16816(O1[j], PA1[nc], v0, v1);
            }
        }
        __syncthreads();   // stage reuse safety for next prefetch
    }

    // ---- epilogue: write fp16 attention output (32 rows per warp) ----
    {
        float inv0 = 1.0f / lrow[0];
        float inv1 = 1.0f / lrow[1];
        float inv2 = 1.0f / lrow[2];
        float inv3 = 1.0f / lrow[3];
        __half* ob = g_aoh + base;
        const int r0 = qt * 128 + warp * 32 + r16;
        #pragma unroll
        for (int j = 0; j < 8; j++) {
            int c = 8 * j + 2 * t4;
            *(uint32_t*)&ob[(long)r0       * 64 + c] =
                cvt2_f16(O0[j][0] * inv0, O0[j][1] * inv0);
            *(uint32_t*)&ob[(long)(r0 + 8) * 64 + c] =
                cvt2_f16(O0[j][2] * inv1, O0[j][3] * inv1);
            *(uint32_t*)&ob[(long)(r0 + 16)* 64 + c] =
                cvt2_f16(O1[j][0] * inv2, O1[j][1] * inv2);
            *(uint32_t*)&ob[(long)(r0 + 24)* 64 + c] =
                cvt2_f16(O1[j][2] * inv3, O1[j][3] * inv3);
        }
    }
}

// ---------------------------------------------------------------------------
// Kernel 3: unify GEMM, fp16 HMMA. Warp owns 32 rows: each W fragment feeds
// 2 MMAs. Block = 128 threads (4 warps) covering 128 rows x 64 cols.
// Dynamic smem 48KB: stage st at st*24576: [A 16KB | W 8KB].
// grid=(EE/64, B*T/128) = (16, 64).
// ---------------------------------------------------------------------------
#define USTG 24576

__global__ __launch_bounds__(128) void unify_kernel(
    const float* __restrict__ bu,
    float* __restrict__ out)
{
    extern __shared__ __align__(16) char smem[];
    const uint32_t aS = smem_u32(smem);

    const int tid  = threadIdx.x;
    const int lane = tid & 31;
    const int warp = tid >> 5;
    const int row0 = blockIdx.y * 128;
    const int col0 = blockIdx.x * 64;
    const int b    = row0 >> 11;       // tiles never straddle b
    const int t0   = row0 & 2047;

    const int t4   = lane & 3;
    const int r16  = lane >> 2;
    const int rl   = lane & 7;
    const int sub  = (lane >> 3) & 1;
    const int half = (lane >> 3) & 1;
    const int kh   = (lane >> 4) & 1;

    auto load_tile = [&](int h, int st) {
        const __half* ga = g_aoh + ((long)(b * HH + h)) * TT * SD + (long)t0 * SD;
        const __half* gw = g_wh + (long)col0 * EE + h * 64;
        const uint32_t so = aS + (uint32_t)st * USTG;
        // A: 128 rows x 64 cols = 1024 granules of 16B; 128 threads x 8
        #pragma unroll
        for (int it = 0; it < 8; it++) {
            int idx = it * 128 + tid;
            int row = idx >> 3, g = idx & 7;
            uint32_t d = (uint32_t)(row * 128 + ((g ^ (row & 7)) * 16));
            cp16(so + d, ga + row * 64 + g * 8);
        }
        // W: 64 rows x 64 cols = 512 granules; 128 threads x 4
        #pragma unroll
        for (int it = 0; it < 4; it++) {
            int idx = it * 128 + tid;
            int row = idx >> 3, g = idx & 7;
            uint32_t d = (uint32_t)(row * 128 + ((g ^ (row & 7)) * 16));
            cp16(so + 16384 + d, gw + (long)row * EE + g * 8);
        }
    };

    float acc0[8][4], acc1[8][4];
    #pragma unroll
    for (int j = 0; j < 8; j++)
        #pragma unroll
        for (int c = 0; c < 4; c++) { acc0[j][c] = 0.f; acc1[j][c] = 0.f; }

    load_tile(0, 0);
    cp_commit();

    for (int h = 0; h < HH; h++) {
        const int st = h & 1;
        const uint32_t so = aS + (uint32_t)st * USTG;
        if (h + 1 < HH) {
            load_tile(h + 1, st ^ 1);
            cp_commit();
            cp_wait<1>();
        } else {
            cp_wait<0>();
        }
        __syncthreads();

        #pragma unroll
        for (int kc = 0; kc < 4; kc++) {
            int arow0 = warp * 32 + rl + 8 * half;
            uint32_t cch = (uint32_t)(((2 * kc + kh) ^ rl) * 16);
            uint32_t A0[4], A1[4];
            ldsm_x4(A0, (uint32_t)(arow0 * 128) + cch + so);
            ldsm_x4(A1, (uint32_t)((arow0 + 16) * 128) + cch + so);
            #pragma unroll
            for (int j = 0; j < 8; j++) {
                uint32_t offW = (uint32_t)((8 * j + rl) * 128 +
                                           (((2 * kc + sub) ^ rl) * 16)) + so + 16384;
                uint32_t w0, w1;
                ldsm_x2(w0, w1, offW);
                mma16816(acc0[j], A0, w0, w1);
                mma16816(acc1[j], A1, w0, w1);
            }
        }
        __syncthreads();
    }

    // store + bias (32 rows per warp)
    {
        const int r0g = row0 + warp * 32 + r16;
        #pragma unroll
        for (int j = 0; j < 8; j++) {
            int c = col0 + 8 * j + 2 * t4;
            float2 bias = *(const float2*)&bu[c];
            *(float2*)&out[(long)r0g       * EE + c] =
                make_float2(acc0[j][0] + bias.x, acc0[j][1] + bias.y);
            *(float2*)&out[(long)(r0g + 8) * EE + c] =
                make_float2(acc0[j][2] + bias.x, acc0[j][3] + bias.y);
            *(float2*)&out[(long)(r0g + 16)* EE + c] =
                make_float2(acc1[j][0] + bias.x, acc1[j][1] + bias.y);
            *(float2*)&out[(long)(r0g + 24)* EE + c] =
                make_float2(acc1[j][2] + bias.x, acc1[j][3] + bias.y);
        }
    }
}

// ---------------------------------------------------------------------------
extern "C" void kernel_launch(void* const* d_in, const int* in_sizes, int n_in,
                              void* d_out, int out_size)
{
    const float* x  = (const float*)d_in[0];
    const float* Wk = (const float*)d_in[1];
    const float* Wq = (const float*)d_in[2];
    const float* Wv = (const float*)d_in[3];
    const float* Wu = (const float*)d_in[4];
    const float* bu = (const float*)d_in[5];
    float* out = (float*)d_out;

    cudaFuncSetAttribute(attn_kernel,
                         cudaFuncAttributeMaxDynamicSharedMemorySize, 32768);
    cudaFuncSetAttribute(unify_kernel,
                         cudaFuncAttributeMaxDynamicSharedMemorySize, 49152);

    wprep_kernel<<<(EE * EE / 4) / 256, 256>>>(Wu);
    qkv_kernel<<<NROWS / 64, 256>>>(x, Wk, Wq, Wv);
    attn_kernel<<<dim3(TT / 128, BB * HH), 128, 32768>>>();
    unify_kernel<<<dim3(EE / 64, (BB * TT) / 128), 128, 49152>>>(bu, out);
}